// round 6
// baseline (speedup 1.0000x reference)
#include <cuda_runtime.h>
#include <cuda_bf16.h>
#include <cstdint>

#define N_NODES 32
#define M_EDGES 256
#define H1 128
#define H2 256
#define H3 128
#define NPAIR 1024
#define EPSF 1e-9f

typedef uint32_t u32;

// ---------------- scratch (no allocations allowed) ----------------
__device__ float g_aT[H1 * N_NODES];
__device__ float g_bT[H1 * N_NODES];
__device__ float g_cT[H1 * M_EDGES];
__device__ float g_preds[NPAIR * M_EDGES];
__device__ float g_A[NPAIR * N_NODES * N_NODES];
__device__ float g_delta[NPAIR * N_NODES];
// Pre-swizzled weight images (smem-image layout, linear-copyable)
__device__ __align__(16) __nv_bfloat16 g_B2img[2][256 * 128];      // [plane][swizzled n*128+k]
__device__ __align__(16) __nv_bfloat16 g_B3img[2][2][128 * 128];   // [kchunk][plane][...]
// h2 activations, bf16 hi/lo planes, row-major per k-chunk: [plane][kchunk][row*128+col]
__device__ __nv_bfloat16 g_h2[2][2][262144 * 128];

// ---------------- PTX helpers ----------------
__device__ __forceinline__ u32 smem_u32(const void* p) {
    u32 a; asm("{ .reg .u64 t; cvta.to.shared.u64 t, %1; cvt.u32.u64 %0, t; }" : "=r"(a) : "l"(p));
    return a;
}
__device__ __forceinline__ void ldm_x4(u32 r[4], u32 addr) {
    asm volatile("ldmatrix.sync.aligned.m8n8.x4.shared.b16 {%0,%1,%2,%3}, [%4];"
                 : "=r"(r[0]), "=r"(r[1]), "=r"(r[2]), "=r"(r[3]) : "r"(addr));
}
__device__ __forceinline__ void ldm_x4_t(u32 r[4], u32 addr) {
    asm volatile("ldmatrix.sync.aligned.m8n8.x4.trans.shared.b16 {%0,%1,%2,%3}, [%4];"
                 : "=r"(r[0]), "=r"(r[1]), "=r"(r[2]), "=r"(r[3]) : "r"(addr));
}
__device__ __forceinline__ void mma16816(float c[4], const u32 a[4], const u32 b[2]) {
    asm volatile("mma.sync.aligned.m16n8k16.row.col.f32.bf16.bf16.f32 "
                 "{%0,%1,%2,%3}, {%4,%5,%6,%7}, {%8,%9}, {%0,%1,%2,%3};"
                 : "+f"(c[0]), "+f"(c[1]), "+f"(c[2]), "+f"(c[3])
                 : "r"(a[0]), "r"(a[1]), "r"(a[2]), "r"(a[3]), "r"(b[0]), "r"(b[1]));
}
__device__ __forceinline__ void cp16(u32 dst, const void* src) {
    asm volatile("cp.async.cg.shared.global [%0], [%1], 16;" :: "r"(dst), "l"(src) : "memory");
}
__device__ __forceinline__ void cp_commit_wait() {
    asm volatile("cp.async.commit_group;" ::: "memory");
    asm volatile("cp.async.wait_group 0;" ::: "memory");
}
__device__ __forceinline__ __nv_bfloat162 split_hi(float v0, float v1, __nv_bfloat162& lo) {
    __nv_bfloat162 hi;
    hi.x = __float2bfloat16(v0); hi.y = __float2bfloat16(v1);
    lo.x = __float2bfloat16(v0 - __bfloat162float(hi.x));
    lo.y = __float2bfloat16(v1 - __bfloat162float(hi.y));
    return hi;
}

// ---------------- kernel 1: factored layer-1 partials ----------------
__global__ void prep_kernel(const float* __restrict__ emb,
                            const int*   __restrict__ edges,
                            const float* __restrict__ W1,
                            const float* __restrict__ b1)
{
    int idx = blockIdx.x * blockDim.x + threadIdx.x;
    if (idx < 2 * H1 * N_NODES) {
        int sec = idx >> 12;
        int r = idx & 4095;
        int k = r >> 5, s = r & 31;
        const float* w = W1 + (sec ? (32 * H1) : 0) + k;
        float acc = 0.f;
        #pragma unroll
        for (int j = 0; j < 32; j++)
            acc = fmaf(emb[s * 32 + j], w[j * H1], acc);
        (sec ? g_bT : g_aT)[k * N_NODES + s] = acc;
    } else {
        int r = idx - 2 * H1 * N_NODES;
        int k = r >> 8, e = r & 255;
        int u = edges[2 * e], v = edges[2 * e + 1];
        const float* wu = W1 + 64 * H1 + k;
        const float* wv = W1 + 96 * H1 + k;
        float acc = b1[k];
        #pragma unroll
        for (int j = 0; j < 32; j++) {
            acc = fmaf(emb[u * 32 + j], wu[j * H1], acc);
            acc = fmaf(emb[v * 32 + j], wv[j * H1], acc);
        }
        g_cT[k * M_EDGES + e] = acc;
    }
}

// ---------------- kernel 1b: split + swizzle weights into smem-image layout ----------------
// Image layout: row = n (out col), 128 k per row, 256B row stride, XOR ((n&7)<<4) on byte off.
__global__ void wprep_kernel(const float* __restrict__ W2, const float* __restrict__ W3)
{
    int idx = blockIdx.x * blockDim.x + threadIdx.x;   // 65536
    int sec = idx >> 15;
    int r = idx & 32767;
    if (sec == 0) {
        int n = r >> 7, k = r & 127;                   // n 0..255, k 0..127
        float w = W2[k * H2 + n];
        __nv_bfloat16 hi = __float2bfloat16(w);
        __nv_bfloat16 lo = __float2bfloat16(w - __bfloat162float(hi));
        u32 off = (u32)(n * 256 + k * 2) ^ (u32)((n & 7) << 4);
        g_B2img[0][off >> 1] = hi;
        g_B2img[1][off >> 1] = lo;
    } else {
        int kg = r >> 7, n = r & 127;                  // kg 0..255, n 0..127
        float w = W3[kg * H3 + n];
        __nv_bfloat16 hi = __float2bfloat16(w);
        __nv_bfloat16 lo = __float2bfloat16(w - __bfloat162float(hi));
        int kc = kg >> 7, kl = kg & 127;
        u32 off = (u32)(n * 256 + kl * 2) ^ (u32)((n & 7) << 4);
        g_B3img[kc][0][off >> 1] = hi;
        g_B3img[kc][1][off >> 1] = lo;
    }
}

// ================= kernel 2a: layer 2 (persistent, B2 resident) =================
// smem: BH 64KB | BL 64KB | A1H 16KB | A1L 16KB  = 160KB
#define L2_BH 0
#define L2_BL 65536
#define L2_A1H 131072
#define L2_A1L (131072 + 16384)
#define L2_SMEM (131072 + 32768)

__global__ void __launch_bounds__(256, 1)
mlp_l2_kernel(const float* __restrict__ b2)
{
    extern __shared__ unsigned char smp[];
    const u32 sb = smem_u32(smp);
    const int tid  = threadIdx.x;
    const int wid  = tid >> 5;
    const int lane = tid & 31;
    const int m0 = (wid >> 2) * 32;        // warp tile 32m x 64n
    const int n0 = (wid & 3) * 64;

    // load resident B2 images (linear copy, pre-swizzled)
    {
        const float4* s0 = (const float4*)g_B2img[0];
        const float4* s1 = (const float4*)g_B2img[1];
        float4* d0 = (float4*)(smp + L2_BH);
        float4* d1 = (float4*)(smp + L2_BL);
        #pragma unroll
        for (int i = 0; i < 16; i++) { d0[tid + i * 256] = s0[tid + i * 256]; }
        #pragma unroll
        for (int i = 0; i < 16; i++) { d1[tid + i * 256] = s1[tid + i * 256]; }
    }

    // per-lane constants
    const int a_krow = (lane & 7) + ((lane >> 4) << 3);   // trans-A k-row within 16
    const int a_cb   = ((lane >> 3) & 1) << 4;            // trans-A m-chunk byte off
    const int b_nrow = ((lane >> 4) << 3) + (lane & 7);   // B n-row within 16
    const int b_kb   = ((lane >> 3) & 1) << 4;            // B k byte off
    const u32 xr     = (u32)((lane & 7) << 4);

    for (int tile = blockIdx.x; tile < 4096; tile += gridDim.x) {
        const int pair = tile >> 2;
        const int eb   = (tile & 3) * 64;
        const int s = pair >> 5, t = pair & 31;

        __syncthreads();   // previous tile fully consumed A1
        // ---- build h1 tile, K-major [128 k][64 m], coalesced ----
        #pragma unroll 4
        for (int j = 0; j < 16; j++) {
            int k = wid + j * 8;
            float base = g_aT[k * 32 + s] + g_bT[k * 32 + t];
            float2 c2 = *(const float2*)&g_cT[k * M_EDGES + eb + lane * 2];
            float v0 = fmaxf(base + c2.x, 0.f);
            float v1 = fmaxf(base + c2.y, 0.f);
            __nv_bfloat162 lp, hp = split_hi(v0, v1, lp);
            u32 off = (u32)(k * 128 + lane * 4) ^ (u32)((k & 7) << 4);
            *(__nv_bfloat162*)(smp + L2_A1H + off) = hp;
            *(__nv_bfloat162*)(smp + L2_A1L + off) = lp;
        }
        __syncthreads();

        // ---- MMA: acc[2][8][4], 3-term split ----
        float acc[2][8][4];
        #pragma unroll
        for (int mt = 0; mt < 2; mt++)
            #pragma unroll
            for (int nt = 0; nt < 8; nt++)
                #pragma unroll
                for (int i = 0; i < 4; i++) acc[mt][nt][i] = 0.f;

        #pragma unroll
        for (int ks = 0; ks < 8; ks++) {
            u32 ah[2][4], al[2][4];
            #pragma unroll
            for (int mt = 0; mt < 2; mt++) {
                u32 off = ((u32)((ks * 16 + a_krow) * 128 + (m0 + mt * 16) * 2 + a_cb)) ^ xr;
                ldm_x4_t(ah[mt], sb + L2_A1H + off);
                ldm_x4_t(al[mt], sb + L2_A1L + off);
            }
            u32 bh[4][4], bl[4][4];
            #pragma unroll
            for (int np = 0; np < 4; np++) {
                u32 off = ((u32)((n0 + np * 16 + b_nrow) * 256 + ks * 32 + b_kb)) ^ xr;
                ldm_x4(bh[np], sb + L2_BH + off);
                ldm_x4(bl[np], sb + L2_BL + off);
            }
            #pragma unroll
            for (int mt = 0; mt < 2; mt++)
                #pragma unroll
                for (int nt = 0; nt < 8; nt++) {
                    const u32* Bh = &bh[nt >> 1][(nt & 1) * 2];
                    const u32* Bl = &bl[nt >> 1][(nt & 1) * 2];
                    mma16816(acc[mt][nt], ah[mt], Bh);
                    mma16816(acc[mt][nt], ah[mt], Bl);
                    mma16816(acc[mt][nt], al[mt], Bh);
                }
        }

        // ---- epilogue: +b2, relu, split, store h2 planes (row-major per k-chunk) ----
        #pragma unroll
        for (int nt = 0; nt < 8; nt++) {
            int n = n0 + nt * 8 + (lane & 3) * 2;
            int chunk = n >> 7, cl = n & 127;
            float bx = __ldg(&b2[n]), by = __ldg(&b2[n + 1]);
            #pragma unroll
            for (int mt = 0; mt < 2; mt++) {
                #pragma unroll
                for (int h = 0; h < 2; h++) {
                    int row_g = tile * 64 + m0 + mt * 16 + (lane >> 2) + h * 8;
                    float v0 = fmaxf(acc[mt][nt][h * 2 + 0] + bx, 0.f);
                    float v1 = fmaxf(acc[mt][nt][h * 2 + 1] + by, 0.f);
                    __nv_bfloat162 lp, hp = split_hi(v0, v1, lp);
                    *(__nv_bfloat162*)&g_h2[0][chunk][row_g * 128 + cl] = hp;
                    *(__nv_bfloat162*)&g_h2[1][chunk][row_g * 128 + cl] = lp;
                }
            }
        }
    }
}

// ================= kernel 2b: layer 3+4 (persistent, B3 resident) =================
// smem: B3 [kc][plane] 4x32KB | A2H 32KB | A2L 32KB | red 2KB = 194KB
#define L3_B 0
#define L3_A2H 131072
#define L3_A2L 163840
#define L3_RED 196608
#define L3_SMEM (196608 + 2048)

__global__ void __launch_bounds__(256, 1)
mlp_l3_kernel(const float* __restrict__ b3, const float* __restrict__ W4,
              const float* __restrict__ b4)
{
    extern __shared__ unsigned char smp[];
    const u32 sb = smem_u32(smp);
    const int tid  = threadIdx.x;
    const int wid  = tid >> 5;
    const int lane = tid & 31;
    const int wn   = wid & 3;
    const int m0 = (wid >> 2) * 64;        // warp tile 64m x 32n
    const int n0 = wn * 32;

    // load resident B3 images
    {
        float4* d = (float4*)(smp + L3_B);
        #pragma unroll
        for (int kc = 0; kc < 2; kc++)
            #pragma unroll
            for (int p = 0; p < 2; p++) {
                const float4* src = (const float4*)g_B3img[kc][p];
                float4* dst = d + (kc * 2 + p) * 2048;
                #pragma unroll
                for (int i = 0; i < 8; i++) dst[tid + i * 256] = src[tid + i * 256];
            }
    }

    const int a_row = (lane & 7) + ((lane >> 3) & 1) * 8;  // non-trans A
    const int a_kb  = (lane >> 4) << 4;
    const int b_nrow = ((lane >> 4) << 3) + (lane & 7);
    const int b_kb   = ((lane >> 3) & 1) << 4;
    const u32 xr     = (u32)((lane & 7) << 4);
    float* red = (float*)(smp + L3_RED);

    const float b4v = __ldg(&b4[0]);

    for (int tile = blockIdx.x; tile < 2048; tile += gridDim.x) {
        const int pair = tile >> 1;
        const int eb   = (tile & 1) * 128;

        float acc3[4][4][4];
        #pragma unroll
        for (int mt = 0; mt < 4; mt++)
            #pragma unroll
            for (int nt = 0; nt < 4; nt++)
                #pragma unroll
                for (int i = 0; i < 4; i++) acc3[mt][nt][i] = 0.f;

        #pragma unroll
        for (int kc = 0; kc < 2; kc++) {
            __syncthreads();   // A2 free (prev chunk/tile consumed; red consumed)
            // ---- stage h2 chunk via cp.async (swizzled dst) ----
            {
                const char* srcH = (const char*)&g_h2[0][kc][(size_t)tile * 128 * 128];
                const char* srcL = (const char*)&g_h2[1][kc][(size_t)tile * 128 * 128];
                #pragma unroll
                for (int i = 0; i < 8; i++) {
                    int f = tid + i * 256;           // 0..2047 16B chunks
                    int row = f >> 4;
                    u32 off = (u32)(f * 16) ^ (u32)((row & 7) << 4);
                    cp16(sb + L3_A2H + off, srcH + f * 16);
                    cp16(sb + L3_A2L + off, srcL + f * 16);
                }
                cp_commit_wait();
            }
            __syncthreads();

            const u32 Bh = sb + L3_B + kc * 65536;
            const u32 Bl = Bh + 32768;
            #pragma unroll
            for (int ks = 0; ks < 8; ks++) {
                u32 ah[4][4], al[4][4];
                #pragma unroll
                for (int mt = 0; mt < 4; mt++) {
                    u32 off = ((u32)((m0 + mt * 16 + a_row) * 256 + ks * 32 + a_kb)) ^ xr;
                    ldm_x4(ah[mt], sb + L3_A2H + off);
                    ldm_x4(al[mt], sb + L3_A2L + off);
                }
                u32 bh[2][4], bl[2][4];
                #pragma unroll
                for (int np = 0; np < 2; np++) {
                    u32 off = ((u32)((n0 + np * 16 + b_nrow) * 256 + ks * 32 + b_kb)) ^ xr;
                    ldm_x4(bh[np], Bh + off);
                    ldm_x4(bl[np], Bl + off);
                }
                #pragma unroll
                for (int mt = 0; mt < 4; mt++)
                    #pragma unroll
                    for (int nt = 0; nt < 4; nt++) {
                        const u32* Bh2 = &bh[nt >> 1][(nt & 1) * 2];
                        const u32* Bl2 = &bl[nt >> 1][(nt & 1) * 2];
                        mma16816(acc3[mt][nt], ah[mt], Bh2);
                        mma16816(acc3[mt][nt], ah[mt], Bl2);
                        mma16816(acc3[mt][nt], al[mt], Bh2);
                    }
            }
        }

        // ---- layer 4 epilogue ----
        #pragma unroll
        for (int mt = 0; mt < 4; mt++) {
            #pragma unroll
            for (int h = 0; h < 2; h++) {
                float part = 0.f;
                #pragma unroll
                for (int nt = 0; nt < 4; nt++) {
                    int c = n0 + nt * 8 + (lane & 3) * 2;
                    float h0 = fmaxf(acc3[mt][nt][h * 2 + 0] + __ldg(&b3[c]), 0.f);
                    float h1 = fmaxf(acc3[mt][nt][h * 2 + 1] + __ldg(&b3[c + 1]), 0.f);
                    part = fmaf(h0, __ldg(&W4[c]), part);
                    part = fmaf(h1, __ldg(&W4[c + 1]), part);
                }
                part += __shfl_xor_sync(0xffffffffu, part, 1);
                part += __shfl_xor_sync(0xffffffffu, part, 2);
                if ((lane & 3) == 0) {
                    int row = m0 + mt * 16 + (lane >> 2) + h * 8;
                    red[wn * 128 + row] = part;
                }
            }
        }
        __syncthreads();
        if (tid < 128) {
            float acc = red[tid] + red[128 + tid] + red[256 + tid] + red[384 + tid];
            g_preds[pair * M_EDGES + eb + tid] = acc + b4v;
        }
    }
}

// ---------------- kernel 3: scatter preds into routing matrices ----------------
__global__ void scatter_kernel(const int* __restrict__ edges)
{
    __shared__ float As[1024];
    int p = blockIdx.x, tid = threadIdx.x;
    #pragma unroll
    for (int i = tid; i < 1024; i += 256) As[i] = 0.f;
    __syncthreads();
    int u = edges[2 * tid], v = edges[2 * tid + 1];
    atomicAdd(&As[u * 32 + v], g_preds[p * M_EDGES + tid]);
    __syncthreads();
    int s = p >> 5;
    int diag = s * 32 + s;
    #pragma unroll
    for (int i = tid; i < 1024; i += 256) {
        float val = As[i];
        if (i == diag) val += 1.f;
        g_A[p * 1024 + i] = val;
    }
}

// ---------------- kernel 4: 50-step power iteration ----------------
__global__ void power_kernel()
{
    int gtid = blockIdx.x * blockDim.x + threadIdx.x;
    int p = gtid >> 5;
    int lane = threadIdx.x & 31;
    const float* Ap = g_A + p * 1024;

    float col[32];
    #pragma unroll
    for (int u = 0; u < 32; u++) col[u] = Ap[u * 32 + lane];

    float x = 1.0f / 32.0f;
    for (int it = 0; it < 50; it++) {
        float acc = 0.f;
        #pragma unroll
        for (int u = 0; u < 32; u++)
            acc = fmaf(__shfl_sync(0xffffffffu, x, u), col[u], acc);
        float ss = acc * acc;
        #pragma unroll
        for (int o = 16; o > 0; o >>= 1)
            ss += __shfl_xor_sync(0xffffffffu, ss, o);
        x = acc / (sqrtf(ss) + EPSF);
    }
    int s = p >> 5, t = p & 31;
    float xs = __shfl_sync(0xffffffffu, x, s);
    float d = (s != t) ? x / (xs + EPSF) : 0.f;
    g_delta[p * 32 + lane] = d;
}

// ---------------- kernel 5: deterministic reduction + normalize ----------------
__global__ void reduce_kernel(float* __restrict__ out)
{
    __shared__ float red[32][33];
    int v = threadIdx.x, g = threadIdx.y;
    float acc = 0.f;
    #pragma unroll 4
    for (int p = g; p < NPAIR; p += 32) acc += g_delta[p * 32 + v];
    red[g][v] = acc;
    __syncthreads();
    #pragma unroll
    for (int st = 16; st > 0; st >>= 1) {
        if (g < st) red[g][v] += red[g + st][v];
        __syncthreads();
    }
    if (g == 0) {
        float r = red[0][v];
        float tot = r;
        #pragma unroll
        for (int o = 16; o > 0; o >>= 1)
            tot += __shfl_xor_sync(0xffffffffu, tot, o);
        out[v] = r / tot;
    }
}

// ---------------- launch ----------------
extern "C" void kernel_launch(void* const* d_in, const int* in_sizes, int n_in,
                              void* d_out, int out_size)
{
    (void)in_sizes; (void)n_in; (void)out_size;
    const float* emb   = (const float*)d_in[1];
    const int*   edges = (const int*)  d_in[2];
    const float* W1 = (const float*)d_in[3];
    const float* b1 = (const float*)d_in[4];
    const float* W2 = (const float*)d_in[5];
    const float* b2 = (const float*)d_in[6];
    const float* W3 = (const float*)d_in[7];
    const float* b3 = (const float*)d_in[8];
    const float* W4 = (const float*)d_in[9];
    const float* b4 = (const float*)d_in[10];
    float* out = (float*)d_out;

    static int attr_set = 0;
    if (!attr_set) {
        cudaFuncSetAttribute(mlp_l2_kernel, cudaFuncAttributeMaxDynamicSharedMemorySize, L2_SMEM);
        cudaFuncSetAttribute(mlp_l3_kernel, cudaFuncAttributeMaxDynamicSharedMemorySize, L3_SMEM);
        attr_set = 1;
    }

    prep_kernel   <<<160, 256>>>(emb, edges, W1, b1);
    wprep_kernel  <<<256, 256>>>(W2, W3);
    mlp_l2_kernel <<<152, 256, L2_SMEM>>>(b2);
    mlp_l3_kernel <<<152, 256, L3_SMEM>>>(b3, W4, b4);
    scatter_kernel<<<1024, 256>>>(edges);
    power_kernel  <<<128, 256>>>();
    reduce_kernel <<<1, dim3(32, 32)>>>(out);
}

// round 9
// speedup vs baseline: 1.9171x; 1.9171x over previous
#include <cuda_runtime.h>
#include <cuda_bf16.h>
#include <cstdint>

#define N_NODES 32
#define M_EDGES 256
#define H1 128
#define H2 256
#define H3 128
#define NPAIR 1024
#define EPSF 1e-9f
#define NTILES 2048          // pair * 2 halves of 128 edge-rows
#define GRID_MLP 152

typedef uint32_t u32;

// ---------------- scratch (no allocations allowed) ----------------
__device__ float g_aT[H1 * N_NODES];
__device__ float g_bT[H1 * N_NODES];
__device__ float g_cT[H1 * M_EDGES];
__device__ float g_preds[NPAIR * M_EDGES];
__device__ float g_A[NPAIR * N_NODES * N_NODES];
__device__ float g_delta[NPAIR * N_NODES];
// 8 cyclic pre-swizzled weight pieces, 32KB each: [hi 16KB | lo 16KB]
// piece 2c   = B2 cols [64c, 64c+64): 64 n-rows x 128 k, 256B rows
// piece 2c+1 = B3 rows [64c, 64c+64): 128 n-rows x 64 k, 128B rows
__device__ __align__(16) unsigned char g_Bseq[8][32768];

// ---------------- smem layout (bytes) ----------------
#define SM_A1H 0                       // h1 hi, [128k][128m], 256B rows, 32KB
#define SM_A1L 32768                   // h1 lo
#define SM_A2H 65536                   // h2 sub hi, [128m][64k], 128B rows, 16KB
#define SM_A2L 81920                   // h2 sub lo
#define SM_B0  98304                   // B ring buf 0 (32KB)
#define SM_B1  131072                  // B ring buf 1 (32KB)
#define SM_RED 163840                  // float[4][128]
#define SM_TOTAL (163840 + 2048)

// ---------------- PTX helpers ----------------
__device__ __forceinline__ u32 smem_u32(const void* p) {
    u32 a; asm("{ .reg .u64 t; cvta.to.shared.u64 t, %1; cvt.u32.u64 %0, t; }" : "=r"(a) : "l"(p));
    return a;
}
__device__ __forceinline__ void ldm_x4(u32 r[4], u32 addr) {
    asm volatile("ldmatrix.sync.aligned.m8n8.x4.shared.b16 {%0,%1,%2,%3}, [%4];"
                 : "=r"(r[0]), "=r"(r[1]), "=r"(r[2]), "=r"(r[3]) : "r"(addr));
}
__device__ __forceinline__ void ldm_x4_t(u32 r[4], u32 addr) {
    asm volatile("ldmatrix.sync.aligned.m8n8.x4.trans.shared.b16 {%0,%1,%2,%3}, [%4];"
                 : "=r"(r[0]), "=r"(r[1]), "=r"(r[2]), "=r"(r[3]) : "r"(addr));
}
__device__ __forceinline__ void mma16816(float c[4], const u32 a[4], const u32 b[2]) {
    asm volatile("mma.sync.aligned.m16n8k16.row.col.f32.bf16.bf16.f32 "
                 "{%0,%1,%2,%3}, {%4,%5,%6,%7}, {%8,%9}, {%0,%1,%2,%3};"
                 : "+f"(c[0]), "+f"(c[1]), "+f"(c[2]), "+f"(c[3])
                 : "r"(a[0]), "r"(a[1]), "r"(a[2]), "r"(a[3]), "r"(b[0]), "r"(b[1]));
}
__device__ __forceinline__ void cp16(u32 dst, const void* src) {
    asm volatile("cp.async.cg.shared.global [%0], [%1], 16;" :: "r"(dst), "l"(src) : "memory");
}
__device__ __forceinline__ void cp_commit() {
    asm volatile("cp.async.commit_group;" ::: "memory");
}
__device__ __forceinline__ void cp_wait0() {
    asm volatile("cp.async.wait_group 0;" ::: "memory");
}
__device__ __forceinline__ __nv_bfloat162 split_hi(float v0, float v1, __nv_bfloat162& lo) {
    __nv_bfloat162 hi;
    hi.x = __float2bfloat16(v0); hi.y = __float2bfloat16(v1);
    lo.x = __float2bfloat16(v0 - __bfloat162float(hi.x));
    lo.y = __float2bfloat16(v1 - __bfloat162float(hi.y));
    return hi;
}

// ---------------- kernel 1: factored layer-1 partials ----------------
__global__ void prep_kernel(const float* __restrict__ emb,
                            const int*   __restrict__ edges,
                            const float* __restrict__ W1,
                            const float* __restrict__ b1)
{
    int idx = blockIdx.x * blockDim.x + threadIdx.x;
    if (idx < 2 * H1 * N_NODES) {
        int sec = idx >> 12;
        int r = idx & 4095;
        int k = r >> 5, s = r & 31;
        const float* w = W1 + (sec ? (32 * H1) : 0) + k;
        float acc = 0.f;
        #pragma unroll
        for (int j = 0; j < 32; j++)
            acc = fmaf(emb[s * 32 + j], w[j * H1], acc);
        (sec ? g_bT : g_aT)[k * N_NODES + s] = acc;
    } else {
        int r = idx - 2 * H1 * N_NODES;
        int k = r >> 8, e = r & 255;
        int u = edges[2 * e], v = edges[2 * e + 1];
        const float* wu = W1 + 64 * H1 + k;
        const float* wv = W1 + 96 * H1 + k;
        float acc = b1[k];
        #pragma unroll
        for (int j = 0; j < 32; j++) {
            acc = fmaf(emb[u * 32 + j], wu[j * H1], acc);
            acc = fmaf(emb[v * 32 + j], wv[j * H1], acc);
        }
        g_cT[k * M_EDGES + e] = acc;
    }
}

// ---------------- kernel 1b: split + swizzle weights into cyclic pieces ----------------
__global__ void wprep_kernel(const float* __restrict__ W2, const float* __restrict__ W3)
{
    int idx = blockIdx.x * blockDim.x + threadIdx.x;   // 65536
    int p = idx >> 13;                                 // piece 0..7
    int r = idx & 8191;
    float w; u32 off;
    if ((p & 1) == 0) {
        int c = p >> 1;
        int nn = r >> 7, k = r & 127;                  // local n row, k col
        w = W2[k * H2 + c * 64 + nn];
        off = (u32)(nn * 256 + k * 2) ^ (u32)((nn & 7) << 4);
    } else {
        int c = p >> 1;
        int n = r >> 6, kl = r & 63;                   // n row, local k col
        w = W3[(c * 64 + kl) * H3 + n];
        off = (u32)(n * 128 + kl * 2) ^ (u32)((n & 7) << 4);
    }
    __nv_bfloat16 hi = __float2bfloat16(w);
    __nv_bfloat16 lo = __float2bfloat16(w - __bfloat162float(hi));
    *(__nv_bfloat16*)&g_Bseq[p][off] = hi;
    *(__nv_bfloat16*)&g_Bseq[p][off + 16384] = lo;
}

// ================= fused MLP: persistent, cp.async double-buffered B =================
__device__ __forceinline__ void issue_piece(u32 dstb, int p, int tid)
{
    const char* src = (const char*)g_Bseq[p];
    #pragma unroll
    for (int i = 0; i < 8; i++) {
        int f = (tid + i * 256) * 16;
        cp16(dstb + f, src + f);
    }
    cp_commit();
}

__global__ void __launch_bounds__(256, 1)
mlp_fused_kernel(const float* __restrict__ b2, const float* __restrict__ b3,
                 const float* __restrict__ W4, const float* __restrict__ b4)
{
    extern __shared__ unsigned char smp[];
    const u32 sb = smem_u32(smp);
    const int tid  = threadIdx.x;
    const int wid  = tid >> 5;
    const int lane = tid & 31;

    // l2 warp layout: 4m x 2n -> warp tile 32m x 32n (N local 64)
    const int m0_2 = (wid >> 1) * 32;
    const int n0_2 = (wid & 1) * 32;
    // l3 warp layout: 2m x 4n -> warp tile 64m x 32n (N 128)
    const int m0_3 = (wid >> 2) * 64;
    const int wn3  = wid & 3;
    const int n0_3 = wn3 * 32;

    // fragment lane constants
    const int a_krow = (lane & 7) + ((lane >> 4) << 3);     // trans-A (l2)
    const int a_cb   = ((lane >> 3) & 1) << 4;
    const int a_row  = (lane & 7) + ((lane >> 3) & 1) * 8;  // non-trans A (l3)
    const int a_kb3  = (lane >> 4) << 4;
    const int b_nrow = ((lane >> 4) << 3) + (lane & 7);     // B rows
    const int b_kb   = ((lane >> 3) & 1) << 4;
    const u32 xl     = (u32)((lane & 7) << 4);              // lane&7 swizzle
    const u32 xk     = (u32)((a_krow & 7) << 4);

    float* red = (float*)(smp + SM_RED);
    const float b4v = __ldg(&b4[0]);
    const u32 bufs[2] = {sb + SM_B0, sb + SM_B1};

    // prefetch piece 0 into buf 0
    issue_piece(bufs[0], 0, tid);

    for (int tile = blockIdx.x; tile < NTILES; tile += GRID_MLP) {
        const int pair = tile >> 1;
        const int eb   = (tile & 1) * 128;
        const int s = pair >> 5, t = pair & 31;

        // ---- build h1 [128k][128m] hi/lo (overlaps piece-0 copy) ----
        #pragma unroll 2
        for (int j = 0; j < 16; j++) {
            int k = wid + j * 8;
            float base = g_aT[k * 32 + s] + g_bT[k * 32 + t];
            u32 swz = (u32)((k & 7) << 4);
            #pragma unroll
            for (int half = 0; half < 2; half++) {
                int m = half * 64 + lane * 2;
                float2 c2 = *(const float2*)&g_cT[k * M_EDGES + eb + m];
                float v0 = fmaxf(base + c2.x, 0.f);
                float v1 = fmaxf(base + c2.y, 0.f);
                __nv_bfloat162 lp, hp = split_hi(v0, v1, lp);
                u32 off = ((u32)(k * 256 + m * 2)) ^ swz;
                *(__nv_bfloat162*)(smp + SM_A1H + off) = hp;
                *(__nv_bfloat162*)(smp + SM_A1L + off) = lp;
            }
        }
        cp_wait0();
        __syncthreads();            // A1 + piece0 ready

        float acc3[4][4][4];
        #pragma unroll
        for (int mt = 0; mt < 4; mt++)
            #pragma unroll
            for (int nt = 0; nt < 4; nt++)
                #pragma unroll
                for (int i = 0; i < 4; i++) acc3[mt][nt][i] = 0.f;

        #pragma unroll 1
        for (int c = 0; c < 4; c++) {
            const u32 bb2 = bufs[0];       // even pieces -> buf0
            const u32 bb3 = bufs[1];       // odd pieces -> buf1

            // prefetch B3 sub c
            issue_piece(bb3, 2 * c + 1, tid);

            // ---- L2 sub-MMA: acc2 = h1 x B2[:, c*64 .. c*64+64) ----
            float acc2[2][4][4];
            #pragma unroll
            for (int mt = 0; mt < 2; mt++)
                #pragma unroll
                for (int nt = 0; nt < 4; nt++)
                    #pragma unroll
                    for (int i = 0; i < 4; i++) acc2[mt][nt][i] = 0.f;

            #pragma unroll
            for (int ks = 0; ks < 8; ks++) {
                u32 ah[2][4], al[2][4];
                #pragma unroll
                for (int mt = 0; mt < 2; mt++) {
                    u32 off = ((u32)((ks * 16 + a_krow) * 256 + (m0_2 + mt * 16) * 2 + a_cb)) ^ xk;
                    ldm_x4_t(ah[mt], sb + SM_A1H + off);
                    ldm_x4_t(al[mt], sb + SM_A1L + off);
                }
                u32 bh[2][4], bl[2][4];
                #pragma unroll
                for (int np = 0; np < 2; np++) {
                    u32 off = ((u32)((n0_2 + np * 16 + b_nrow) * 256 + ks * 32 + b_kb)) ^ xl;
                    ldm_x4(bh[np], bb2 + off);
                    ldm_x4(bl[np], bb2 + 16384 + off);
                }
                #pragma unroll
                for (int mt = 0; mt < 2; mt++)
                    #pragma unroll
                    for (int nt = 0; nt < 4; nt++) {
                        const u32* Bh = &bh[nt >> 1][(nt & 1) * 2];
                        const u32* Bl = &bl[nt >> 1][(nt & 1) * 2];
                        mma16816(acc2[mt][nt], ah[mt], Bh);
                        mma16816(acc2[mt][nt], ah[mt], Bl);
                        mma16816(acc2[mt][nt], al[mt], Bh);
                    }
            }

            // ---- h2 epilogue -> A2 [128m][64k] ----
            #pragma unroll
            for (int nt = 0; nt < 4; nt++) {
                int nl = n0_2 + nt * 8 + (lane & 3) * 2;
                int gc = c * 64 + nl;
                float bx = __ldg(&b2[gc]), by = __ldg(&b2[gc + 1]);
                #pragma unroll
                for (int mt = 0; mt < 2; mt++) {
                    #pragma unroll
                    for (int h = 0; h < 2; h++) {
                        int row = m0_2 + mt * 16 + (lane >> 2) + h * 8;
                        float v0 = fmaxf(acc2[mt][nt][h * 2 + 0] + bx, 0.f);
                        float v1 = fmaxf(acc2[mt][nt][h * 2 + 1] + by, 0.f);
                        __nv_bfloat162 lp, hp = split_hi(v0, v1, lp);
                        u32 off = ((u32)(row * 128 + nl * 2)) ^ (u32)((row & 7) << 4);
                        *(__nv_bfloat162*)(smp + SM_A2H + off) = hp;
                        *(__nv_bfloat162*)(smp + SM_A2L + off) = lp;
                    }
                }
            }
            cp_wait0();
            __syncthreads();        // A2 visible + B3 piece ready

            // prefetch next even piece (B2 sub c+1, wraps to 0 for next tile)
            issue_piece(bb2, (2 * c + 2) & 7, tid);

            // ---- L3 sub-MMA: acc3 += h2c x B3[c*64.., :] ----
            #pragma unroll
            for (int ks = 0; ks < 4; ks++) {
                u32 ah[4][4], al[4][4];
                #pragma unroll
                for (int mt = 0; mt < 4; mt++) {
                    u32 off = ((u32)((m0_3 + mt * 16 + a_row) * 128 + ks * 32 + a_kb3)) ^ xl;
                    ldm_x4(ah[mt], sb + SM_A2H + off);
                    ldm_x4(al[mt], sb + SM_A2L + off);
                }
                u32 bh[2][4], bl[2][4];
                #pragma unroll
                for (int np = 0; np < 2; np++) {
                    u32 off = ((u32)((n0_3 + np * 16 + b_nrow) * 128 + ks * 32 + b_kb)) ^ xl;
                    ldm_x4(bh[np], bb3 + off);
                    ldm_x4(bl[np], bb3 + 16384 + off);
                }
                #pragma unroll
                for (int mt = 0; mt < 4; mt++)
                    #pragma unroll
                    for (int nt = 0; nt < 4; nt++) {
                        const u32* Bh = &bh[nt >> 1][(nt & 1) * 2];
                        const u32* Bl = &bl[nt >> 1][(nt & 1) * 2];
                        mma16816(acc3[mt][nt], ah[mt], Bh);
                        mma16816(acc3[mt][nt], ah[mt], Bl);
                        mma16816(acc3[mt][nt], al[mt], Bh);
                    }
            }
            cp_wait0();
            __syncthreads();        // A2 free for next epilogue + next B2 ready
        }

        // ---- layer 4: pred = relu(h3 + b3) . W4 + b4 ----
        #pragma unroll
        for (int mt = 0; mt < 4; mt++) {
            #pragma unroll
            for (int h = 0; h < 2; h++) {
                float part = 0.f;
                #pragma unroll
                for (int nt = 0; nt < 4; nt++) {
                    int cc = n0_3 + nt * 8 + (lane & 3) * 2;
                    float h0 = fmaxf(acc3[mt][nt][h * 2 + 0] + __ldg(&b3[cc]), 0.f);
                    float h1 = fmaxf(acc3[mt][nt][h * 2 + 1] + __ldg(&b3[cc + 1]), 0.f);
                    part = fmaf(h0, __ldg(&W4[cc]), part);
                    part = fmaf(h1, __ldg(&W4[cc + 1]), part);
                }
                part += __shfl_xor_sync(0xffffffffu, part, 1);
                part += __shfl_xor_sync(0xffffffffu, part, 2);
                if ((lane & 3) == 0) {
                    int row = m0_3 + mt * 16 + (lane >> 2) + h * 8;
                    red[wn3 * 128 + row] = part;
                }
            }
        }
        __syncthreads();
        if (tid < 128) {
            float acc = red[tid] + red[128 + tid] + red[256 + tid] + red[384 + tid];
            g_preds[pair * M_EDGES + eb + tid] = acc + b4v;
        }
        __syncthreads();            // red consumed before next tile reuses smem
    }
    cp_wait0();                     // drain trailing prefetch
}

// ---------------- kernel 3: scatter preds into routing matrices ----------------
__global__ void scatter_kernel(const int* __restrict__ edges)
{
    __shared__ float As[1024];
    int p = blockIdx.x, tid = threadIdx.x;
    #pragma unroll
    for (int i = tid; i < 1024; i += 256) As[i] = 0.f;
    __syncthreads();
    int u = edges[2 * tid], v = edges[2 * tid + 1];
    atomicAdd(&As[u * 32 + v], g_preds[p * M_EDGES + tid]);
    __syncthreads();
    int s = p >> 5;
    int diag = s * 32 + s;
    #pragma unroll
    for (int i = tid; i < 1024; i += 256) {
        float val = As[i];
        if (i == diag) val += 1.f;
        g_A[p * 1024 + i] = val;
    }
}

// ---------------- kernel 4: 50-step power iteration ----------------
__global__ void power_kernel()
{
    int gtid = blockIdx.x * blockDim.x + threadIdx.x;
    int p = gtid >> 5;
    int lane = threadIdx.x & 31;
    const float* Ap = g_A + p * 1024;

    float col[32];
    #pragma unroll
    for (int u = 0; u < 32; u++) col[u] = Ap[u * 32 + lane];

    float x = 1.0f / 32.0f;
    for (int it = 0; it < 50; it++) {
        float acc = 0.f;
        #pragma unroll
        for (int u = 0; u < 32; u++)
            acc = fmaf(__shfl_sync(0xffffffffu, x, u), col[u], acc);
        float ss = acc * acc;
        #pragma unroll
        for (int o = 16; o > 0; o >>= 1)
            ss += __shfl_xor_sync(0xffffffffu, ss, o);
        x = acc / (sqrtf(ss) + EPSF);
    }
    int s = p >> 5, t = p & 31;
    float xs = __shfl_sync(0xffffffffu, x, s);
    float d = (s != t) ? x / (xs + EPSF) : 0.f;
    g_delta[p * 32 + lane] = d;
}

// ---------------- kernel 5: deterministic reduction + normalize ----------------
__global__ void reduce_kernel(float* __restrict__ out)
{
    __shared__ float red[32][33];
    int v = threadIdx.x, g = threadIdx.y;
    float acc = 0.f;
    #pragma unroll 4
    for (int p = g; p < NPAIR; p += 32) acc += g_delta[p * 32 + v];
    red[g][v] = acc;
    __syncthreads();
    #pragma unroll
    for (int st = 16; st > 0; st >>= 1) {
        if (g < st) red[g][v] += red[g + st][v];
        __syncthreads();
    }
    if (g == 0) {
        float r = red[0][v];
        float tot = r;
        #pragma unroll
        for (int o = 16; o > 0; o >>= 1)
            tot += __shfl_xor_sync(0xffffffffu, tot, o);
        out[v] = r / tot;
    }
}

// ---------------- launch ----------------
extern "C" void kernel_launch(void* const* d_in, const int* in_sizes, int n_in,
                              void* d_out, int out_size)
{
    (void)in_sizes; (void)n_in; (void)out_size;
    const float* emb   = (const float*)d_in[1];
    const int*   edges = (const int*)  d_in[2];
    const float* W1 = (const float*)d_in[3];
    const float* b1 = (const float*)d_in[4];
    const float* W2 = (const float*)d_in[5];
    const float* b2 = (const float*)d_in[6];
    const float* W3 = (const float*)d_in[7];
    const float* b3 = (const float*)d_in[8];
    const float* W4 = (const float*)d_in[9];
    const float* b4 = (const float*)d_in[10];
    float* out = (float*)d_out;

    static int attr_set = 0;
    if (!attr_set) {
        cudaFuncSetAttribute(mlp_fused_kernel, cudaFuncAttributeMaxDynamicSharedMemorySize, SM_TOTAL);
        attr_set = 1;
    }

    prep_kernel     <<<160, 256>>>(emb, edges, W1, b1);
    wprep_kernel    <<<256, 256>>>(W2, W3);
    mlp_fused_kernel<<<GRID_MLP, 256, SM_TOTAL>>>(b2, b3, W4, b4);
    scatter_kernel  <<<1024, 256>>>(edges);
    power_kernel    <<<128, 256>>>();
    reduce_kernel   <<<1, dim3(32, 32)>>>(out);
}

// round 10
// speedup vs baseline: 1.9826x; 1.0342x over previous
#include <cuda_runtime.h>
#include <cuda_bf16.h>
#include <cstdint>

#define N_NODES 32
#define M_EDGES 256
#define H1 128
#define H2 256
#define H3 128
#define NPAIR 1024
#define EPSF 1e-9f
#define NTILES 2048          // pair * 2 halves of 128 edge-rows
#define GRID_MLP 152
#define NTHREADS 512

typedef uint32_t u32;

// ---------------- scratch (no allocations allowed) ----------------
__device__ float g_aT[H1 * N_NODES];
__device__ float g_bT[H1 * N_NODES];
__device__ float g_cT[H1 * M_EDGES];
__device__ float g_preds[NPAIR * M_EDGES];
__device__ float g_A[NPAIR * N_NODES * N_NODES];
__device__ float g_delta[NPAIR * N_NODES];
// 8 cyclic pre-swizzled weight pieces, 32KB each: [hi 16KB | lo 16KB]
__device__ __align__(16) unsigned char g_Bseq[8][32768];

// ---------------- smem layout (bytes) ----------------
#define SM_A1H 0                       // h1 hi, [128k][128m], 256B rows, 32KB
#define SM_A1L 32768                   // h1 lo
#define SM_A2H 65536                   // h2 sub hi, [128m][64k], 128B rows, 16KB
#define SM_A2L 81920                   // h2 sub lo
#define SM_B0  98304                   // B ring buf 0 (32KB)
#define SM_B1  131072                  // B ring buf 1 (32KB)
#define SM_RED 163840                  // float[4][128]
#define SM_TOTAL (163840 + 2048)

// ---------------- PTX helpers ----------------
__device__ __forceinline__ u32 smem_u32(const void* p) {
    u32 a; asm("{ .reg .u64 t; cvta.to.shared.u64 t, %1; cvt.u32.u64 %0, t; }" : "=r"(a) : "l"(p));
    return a;
}
__device__ __forceinline__ void ldm_x4(u32 r[4], u32 addr) {
    asm volatile("ldmatrix.sync.aligned.m8n8.x4.shared.b16 {%0,%1,%2,%3}, [%4];"
                 : "=r"(r[0]), "=r"(r[1]), "=r"(r[2]), "=r"(r[3]) : "r"(addr));
}
__device__ __forceinline__ void ldm_x4_t(u32 r[4], u32 addr) {
    asm volatile("ldmatrix.sync.aligned.m8n8.x4.trans.shared.b16 {%0,%1,%2,%3}, [%4];"
                 : "=r"(r[0]), "=r"(r[1]), "=r"(r[2]), "=r"(r[3]) : "r"(addr));
}
__device__ __forceinline__ void mma16816(float c[4], const u32 a[4], const u32 b[2]) {
    asm volatile("mma.sync.aligned.m16n8k16.row.col.f32.bf16.bf16.f32 "
                 "{%0,%1,%2,%3}, {%4,%5,%6,%7}, {%8,%9}, {%0,%1,%2,%3};"
                 : "+f"(c[0]), "+f"(c[1]), "+f"(c[2]), "+f"(c[3])
                 : "r"(a[0]), "r"(a[1]), "r"(a[2]), "r"(a[3]), "r"(b[0]), "r"(b[1]));
}
__device__ __forceinline__ void cp16(u32 dst, const void* src) {
    asm volatile("cp.async.cg.shared.global [%0], [%1], 16;" :: "r"(dst), "l"(src) : "memory");
}
__device__ __forceinline__ void cp_commit() {
    asm volatile("cp.async.commit_group;" ::: "memory");
}
__device__ __forceinline__ void cp_wait0() {
    asm volatile("cp.async.wait_group 0;" ::: "memory");
}
__device__ __forceinline__ __nv_bfloat162 split_hi(float v0, float v1, __nv_bfloat162& lo) {
    __nv_bfloat162 hi;
    hi.x = __float2bfloat16(v0); hi.y = __float2bfloat16(v1);
    lo.x = __float2bfloat16(v0 - __bfloat162float(hi.x));
    lo.y = __float2bfloat16(v1 - __bfloat162float(hi.y));
    return hi;
}

// ---------------- kernel 1: factored layer-1 partials ----------------
__global__ void prep_kernel(const float* __restrict__ emb,
                            const int*   __restrict__ edges,
                            const float* __restrict__ W1,
                            const float* __restrict__ b1)
{
    int idx = blockIdx.x * blockDim.x + threadIdx.x;
    if (idx < 2 * H1 * N_NODES) {
        int sec = idx >> 12;
        int r = idx & 4095;
        int k = r >> 5, s = r & 31;
        const float* w = W1 + (sec ? (32 * H1) : 0) + k;
        float acc = 0.f;
        #pragma unroll
        for (int j = 0; j < 32; j++)
            acc = fmaf(emb[s * 32 + j], w[j * H1], acc);
        (sec ? g_bT : g_aT)[k * N_NODES + s] = acc;
    } else {
        int r = idx - 2 * H1 * N_NODES;
        int k = r >> 8, e = r & 255;
        int u = edges[2 * e], v = edges[2 * e + 1];
        const float* wu = W1 + 64 * H1 + k;
        const float* wv = W1 + 96 * H1 + k;
        float acc = b1[k];
        #pragma unroll
        for (int j = 0; j < 32; j++) {
            acc = fmaf(emb[u * 32 + j], wu[j * H1], acc);
            acc = fmaf(emb[v * 32 + j], wv[j * H1], acc);
        }
        g_cT[k * M_EDGES + e] = acc;
    }
}

// ---------------- kernel 1b: split + swizzle weights into cyclic pieces ----------------
__global__ void wprep_kernel(const float* __restrict__ W2, const float* __restrict__ W3)
{
    int idx = blockIdx.x * blockDim.x + threadIdx.x;   // 65536
    int p = idx >> 13;                                 // piece 0..7
    int r = idx & 8191;
    float w; u32 off;
    if ((p & 1) == 0) {
        int c = p >> 1;
        int nn = r >> 7, k = r & 127;
        w = W2[k * H2 + c * 64 + nn];
        off = (u32)(nn * 256 + k * 2) ^ (u32)((nn & 7) << 4);
    } else {
        int c = p >> 1;
        int n = r >> 6, kl = r & 63;
        w = W3[(c * 64 + kl) * H3 + n];
        off = (u32)(n * 128 + kl * 2) ^ (u32)((n & 7) << 4);
    }
    __nv_bfloat16 hi = __float2bfloat16(w);
    __nv_bfloat16 lo = __float2bfloat16(w - __bfloat162float(hi));
    *(__nv_bfloat16*)&g_Bseq[p][off] = hi;
    *(__nv_bfloat16*)&g_Bseq[p][off + 16384] = lo;
}

// ================= fused MLP: persistent, 512 threads, cp.async double-buffered B =================
__device__ __forceinline__ void issue_piece(u32 dstb, int p, int tid)
{
    const char* src = (const char*)g_Bseq[p];
    #pragma unroll
    for (int i = 0; i < 4; i++) {
        int f = (tid + i * NTHREADS) * 16;
        cp16(dstb + f, src + f);
    }
    cp_commit();
}

__global__ void __launch_bounds__(NTHREADS, 1)
mlp_fused_kernel(const float* __restrict__ b2, const float* __restrict__ b3,
                 const float* __restrict__ W4, const float* __restrict__ b4)
{
    extern __shared__ unsigned char smp[];
    const u32 sb = smem_u32(smp);
    const int tid  = threadIdx.x;
    const int wid  = tid >> 5;            // 0..15
    const int lane = tid & 31;

    // l2 warp layout: 4m x 4n -> warp tile 32m x 16n (N local 64)
    const int m0_2 = (wid >> 2) * 32;
    const int n0_2 = (wid & 3) * 16;
    // l3 warp layout: 4m x 4n -> warp tile 32m x 32n (N 128)
    const int m0_3 = (wid >> 2) * 32;
    const int wn3  = wid & 3;
    const int n0_3 = wn3 * 32;

    // fragment lane constants
    const int a_krow = (lane & 7) + ((lane >> 4) << 3);     // trans-A (l2)
    const int a_cb   = ((lane >> 3) & 1) << 4;
    const int a_row  = (lane & 7) + ((lane >> 3) & 1) * 8;  // non-trans A (l3)
    const int a_kb3  = (lane >> 4) << 4;
    const int b_nrow = ((lane >> 4) << 3) + (lane & 7);     // B rows
    const int b_kb   = ((lane >> 3) & 1) << 4;
    const u32 xl     = (u32)((lane & 7) << 4);
    const u32 xk     = (u32)((a_krow & 7) << 4);

    float* red = (float*)(smp + SM_RED);
    const float b4v = __ldg(&b4[0]);
    const u32 bufs[2] = {sb + SM_B0, sb + SM_B1};

    // prefetch piece 0 into buf 0
    issue_piece(bufs[0], 0, tid);

    for (int tile = blockIdx.x; tile < NTILES; tile += GRID_MLP) {
        const int pair = tile >> 1;
        const int eb   = (tile & 1) * 128;
        const int s = pair >> 5, t = pair & 31;

        // ---- build h1 [128k][128m] hi/lo (16 warps: k = wid + 16j, m = lane*4) ----
        #pragma unroll
        for (int j = 0; j < 8; j++) {
            int k = wid + j * 16;
            float base = g_aT[k * 32 + s] + g_bT[k * 32 + t];
            u32 swz = (u32)((k & 7) << 4);
            int m = lane * 4;
            float4 c4 = *(const float4*)&g_cT[k * M_EDGES + eb + m];
            float v0 = fmaxf(base + c4.x, 0.f);
            float v1 = fmaxf(base + c4.y, 0.f);
            float v2 = fmaxf(base + c4.z, 0.f);
            float v3 = fmaxf(base + c4.w, 0.f);
            __nv_bfloat162 lp0, hp0 = split_hi(v0, v1, lp0);
            __nv_bfloat162 lp1, hp1 = split_hi(v2, v3, lp1);
            u32 off = ((u32)(k * 256 + m * 2)) ^ swz;
            *(__nv_bfloat162*)(smp + SM_A1H + off)     = hp0;
            *(__nv_bfloat162*)(smp + SM_A1H + off + 4) = hp1;
            *(__nv_bfloat162*)(smp + SM_A1L + off)     = lp0;
            *(__nv_bfloat162*)(smp + SM_A1L + off + 4) = lp1;
        }
        cp_wait0();
        __syncthreads();            // A1 + piece0 ready

        float acc3[2][4][4];
        #pragma unroll
        for (int mt = 0; mt < 2; mt++)
            #pragma unroll
            for (int nt = 0; nt < 4; nt++)
                #pragma unroll
                for (int i = 0; i < 4; i++) acc3[mt][nt][i] = 0.f;

        #pragma unroll 1
        for (int c = 0; c < 4; c++) {
            const u32 bb2 = bufs[0];       // even pieces -> buf0
            const u32 bb3 = bufs[1];       // odd pieces -> buf1

            // prefetch B3 sub c
            issue_piece(bb3, 2 * c + 1, tid);

            // ---- L2 sub-MMA: acc2 = h1 x B2[:, c*64 .. c*64+64) ----
            float acc2[2][2][4];
            #pragma unroll
            for (int mt = 0; mt < 2; mt++)
                #pragma unroll
                for (int nt = 0; nt < 2; nt++)
                    #pragma unroll
                    for (int i = 0; i < 4; i++) acc2[mt][nt][i] = 0.f;

            #pragma unroll
            for (int ks = 0; ks < 8; ks++) {
                u32 ah[2][4], al[2][4];
                #pragma unroll
                for (int mt = 0; mt < 2; mt++) {
                    u32 off = ((u32)((ks * 16 + a_krow) * 256 + (m0_2 + mt * 16) * 2 + a_cb)) ^ xk;
                    ldm_x4_t(ah[mt], sb + SM_A1H + off);
                    ldm_x4_t(al[mt], sb + SM_A1L + off);
                }
                u32 bh[4], bl[4];
                {
                    u32 off = ((u32)((n0_2 + b_nrow) * 256 + ks * 32 + b_kb)) ^ xl;
                    ldm_x4(bh, bb2 + off);
                    ldm_x4(bl, bb2 + 16384 + off);
                }
                #pragma unroll
                for (int mt = 0; mt < 2; mt++)
                    #pragma unroll
                    for (int nt = 0; nt < 2; nt++) {
                        const u32* Bh = &bh[nt * 2];
                        const u32* Bl = &bl[nt * 2];
                        mma16816(acc2[mt][nt], ah[mt], Bh);
                        mma16816(acc2[mt][nt], ah[mt], Bl);
                        mma16816(acc2[mt][nt], al[mt], Bh);
                    }
            }

            // ---- h2 epilogue -> A2 [128m][64k] ----
            #pragma unroll
            for (int nt = 0; nt < 2; nt++) {
                int nl = n0_2 + nt * 8 + (lane & 3) * 2;
                int gc = c * 64 + nl;
                float bx = __ldg(&b2[gc]), by = __ldg(&b2[gc + 1]);
                #pragma unroll
                for (int mt = 0; mt < 2; mt++) {
                    #pragma unroll
                    for (int h = 0; h < 2; h++) {
                        int row = m0_2 + mt * 16 + (lane >> 2) + h * 8;
                        float v0 = fmaxf(acc2[mt][nt][h * 2 + 0] + bx, 0.f);
                        float v1 = fmaxf(acc2[mt][nt][h * 2 + 1] + by, 0.f);
                        __nv_bfloat162 lp, hp = split_hi(v0, v1, lp);
                        u32 off = ((u32)(row * 128 + nl * 2)) ^ (u32)((row & 7) << 4);
                        *(__nv_bfloat162*)(smp + SM_A2H + off) = hp;
                        *(__nv_bfloat162*)(smp + SM_A2L + off) = lp;
                    }
                }
            }
            cp_wait0();
            __syncthreads();        // A2 visible + B3 piece ready

            // prefetch next even piece (wraps to 0 for next tile)
            issue_piece(bb2, (2 * c + 2) & 7, tid);

            // ---- L3 sub-MMA: acc3 += h2c x B3[c*64.., :] ----
            #pragma unroll
            for (int ks = 0; ks < 4; ks++) {
                u32 ah[2][4], al[2][4];
                #pragma unroll
                for (int mt = 0; mt < 2; mt++) {
                    u32 off = ((u32)((m0_3 + mt * 16 + a_row) * 128 + ks * 32 + a_kb3)) ^ xl;
                    ldm_x4(ah[mt], sb + SM_A2H + off);
                    ldm_x4(al[mt], sb + SM_A2L + off);
                }
                u32 bh[2][4], bl[2][4];
                #pragma unroll
                for (int np = 0; np < 2; np++) {
                    u32 off = ((u32)((n0_3 + np * 16 + b_nrow) * 128 + ks * 32 + b_kb)) ^ xl;
                    ldm_x4(bh[np], bb3 + off);
                    ldm_x4(bl[np], bb3 + 16384 + off);
                }
                #pragma unroll
                for (int mt = 0; mt < 2; mt++)
                    #pragma unroll
                    for (int nt = 0; nt < 4; nt++) {
                        const u32* Bh = &bh[nt >> 1][(nt & 1) * 2];
                        const u32* Bl = &bl[nt >> 1][(nt & 1) * 2];
                        mma16816(acc3[mt][nt], ah[mt], Bh);
                        mma16816(acc3[mt][nt], ah[mt], Bl);
                        mma16816(acc3[mt][nt], al[mt], Bh);
                    }
            }
            cp_wait0();
            __syncthreads();        // A2 free for next epilogue + next B2 ready
        }

        // ---- layer 4: pred = relu(h3 + b3) . W4 + b4 ----
        #pragma unroll
        for (int mt = 0; mt < 2; mt++) {
            #pragma unroll
            for (int h = 0; h < 2; h++) {
                float part = 0.f;
                #pragma unroll
                for (int nt = 0; nt < 4; nt++) {
                    int cc = n0_3 + nt * 8 + (lane & 3) * 2;
                    float h0 = fmaxf(acc3[mt][nt][h * 2 + 0] + __ldg(&b3[cc]), 0.f);
                    float h1 = fmaxf(acc3[mt][nt][h * 2 + 1] + __ldg(&b3[cc + 1]), 0.f);
                    part = fmaf(h0, __ldg(&W4[cc]), part);
                    part = fmaf(h1, __ldg(&W4[cc + 1]), part);
                }
                part += __shfl_xor_sync(0xffffffffu, part, 1);
                part += __shfl_xor_sync(0xffffffffu, part, 2);
                if ((lane & 3) == 0) {
                    int row = m0_3 + mt * 16 + (lane >> 2) + h * 8;
                    red[wn3 * 128 + row] = part;
                }
            }
        }
        __syncthreads();
        if (tid < 128) {
            float acc = red[tid] + red[128 + tid] + red[256 + tid] + red[384 + tid];
            g_preds[pair * M_EDGES + eb + tid] = acc + b4v;
        }
        __syncthreads();            // red consumed before next tile reuses smem
    }
    cp_wait0();
}

// ---------------- kernel 3: scatter preds into routing matrices ----------------
__global__ void scatter_kernel(const int* __restrict__ edges)
{
    __shared__ float As[1024];
    int p = blockIdx.x, tid = threadIdx.x;
    #pragma unroll
    for (int i = tid; i < 1024; i += 256) As[i] = 0.f;
    __syncthreads();
    int u = edges[2 * tid], v = edges[2 * tid + 1];
    atomicAdd(&As[u * 32 + v], g_preds[p * M_EDGES + tid]);
    __syncthreads();
    int s = p >> 5;
    int diag = s * 32 + s;
    #pragma unroll
    for (int i = tid; i < 1024; i += 256) {
        float val = As[i];
        if (i == diag) val += 1.f;
        g_A[p * 1024 + i] = val;
    }
}

// ---------------- kernel 4: 50-step power iteration ----------------
__global__ void power_kernel()
{
    int gtid = blockIdx.x * blockDim.x + threadIdx.x;
    int p = gtid >> 5;
    int lane = threadIdx.x & 31;
    const float* Ap = g_A + p * 1024;

    float col[32];
    #pragma unroll
    for (int u = 0; u < 32; u++) col[u] = Ap[u * 32 + lane];

    float x = 1.0f / 32.0f;
    for (int it = 0; it < 50; it++) {
        float acc = 0.f;
        #pragma unroll
        for (int u = 0; u < 32; u++)
            acc = fmaf(__shfl_sync(0xffffffffu, x, u), col[u], acc);
        float ss = acc * acc;
        #pragma unroll
        for (int o = 16; o > 0; o >>= 1)
            ss += __shfl_xor_sync(0xffffffffu, ss, o);
        x = acc / (sqrtf(ss) + EPSF);
    }
    int s = p >> 5, t = p & 31;
    float xs = __shfl_sync(0xffffffffu, x, s);
    float d = (s != t) ? x / (xs + EPSF) : 0.f;
    g_delta[p * 32 + lane] = d;
}

// ---------------- kernel 5: deterministic reduction + normalize ----------------
__global__ void reduce_kernel(float* __restrict__ out)
{
    __shared__ float red[32][33];
    int v = threadIdx.x, g = threadIdx.y;
    float acc = 0.f;
    #pragma unroll 4
    for (int p = g; p < NPAIR; p += 32) acc += g_delta[p * 32 + v];
    red[g][v] = acc;
    __syncthreads();
    #pragma unroll
    for (int st = 16; st > 0; st >>= 1) {
        if (g < st) red[g][v] += red[g + st][v];
        __syncthreads();
    }
    if (g == 0) {
        float r = red[0][v];
        float tot = r;
        #pragma unroll
        for (int o = 16; o > 0; o >>= 1)
            tot += __shfl_xor_sync(0xffffffffu, tot, o);
        out[v] = r / tot;
    }
}

// ---------------- launch ----------------
extern "C" void kernel_launch(void* const* d_in, const int* in_sizes, int n_in,
                              void* d_out, int out_size)
{
    (void)in_sizes; (void)n_in; (void)out_size;
    const float* emb   = (const float*)d_in[1];
    const int*   edges = (const int*)  d_in[2];
    const float* W1 = (const float*)d_in[3];
    const float* b1 = (const float*)d_in[4];
    const float* W2 = (const float*)d_in[5];
    const float* b2 = (const float*)d_in[6];
    const float* W3 = (const float*)d_in[7];
    const float* b3 = (const float*)d_in[8];
    const float* W4 = (const float*)d_in[9];
    const float* b4 = (const float*)d_in[10];
    float* out = (float*)d_out;

    static int attr_set = 0;
    if (!attr_set) {
        cudaFuncSetAttribute(mlp_fused_kernel, cudaFuncAttributeMaxDynamicSharedMemorySize, SM_TOTAL);
        attr_set = 1;
    }

    prep_kernel     <<<160, 256>>>(emb, edges, W1, b1);
    wprep_kernel    <<<256, 256>>>(W2, W3);
    mlp_fused_kernel<<<GRID_MLP, NTHREADS, SM_TOTAL>>>(b2, b3, W4, b4);
    scatter_kernel  <<<1024, 256>>>(edges);
    power_kernel    <<<128, 256>>>();
    reduce_kernel   <<<1, dim3(32, 32)>>>(out);
}

// round 11
// speedup vs baseline: 1.9828x; 1.0001x over previous
#include <cuda_runtime.h>
#include <cuda_bf16.h>
#include <cstdint>

#define N_NODES 32
#define M_EDGES 256
#define H1 128
#define H2 256
#define H3 128
#define NPAIR 1024
#define EPSF 1e-9f
#define NTILES 2048          // pair * 2 halves of 128 edge-rows
#define GRID_MLP 152
#define NTHREADS 512

typedef uint32_t u32;

// ---------------- scratch (no allocations allowed) ----------------
__device__ float g_aT[H1 * N_NODES];
__device__ float g_bT[H1 * N_NODES];
__device__ float g_cT[H1 * M_EDGES];
__device__ float g_preds[NPAIR * M_EDGES];
__device__ float g_delta[NPAIR * N_NODES];
// 8 cyclic pre-swizzled weight pieces, 32KB each: [hi 16KB | lo 16KB]
__device__ __align__(16) unsigned char g_Bseq[8][32768];

// ---------------- smem layout (bytes) ----------------
#define SM_A1H 0                       // h1 hi, [128k][128m], 256B rows, 32KB
#define SM_A1L 32768                   // h1 lo
#define SM_A2H 65536                   // h2 sub hi, [128m][64k], 128B rows, 16KB
#define SM_A2L 81920                   // h2 sub lo
#define SM_B0  98304                   // B ring buf 0 (32KB)
#define SM_B1  131072                  // B ring buf 1 (32KB)
#define SM_RED 163840                  // float[4][128]
#define SM_TOTAL (163840 + 2048)

// ---------------- PTX helpers ----------------
__device__ __forceinline__ u32 smem_u32(const void* p) {
    u32 a; asm("{ .reg .u64 t; cvta.to.shared.u64 t, %1; cvt.u32.u64 %0, t; }" : "=r"(a) : "l"(p));
    return a;
}
__device__ __forceinline__ void ldm_x4(u32 r[4], u32 addr) {
    asm volatile("ldmatrix.sync.aligned.m8n8.x4.shared.b16 {%0,%1,%2,%3}, [%4];"
                 : "=r"(r[0]), "=r"(r[1]), "=r"(r[2]), "=r"(r[3]) : "r"(addr));
}
__device__ __forceinline__ void ldm_x4_t(u32 r[4], u32 addr) {
    asm volatile("ldmatrix.sync.aligned.m8n8.x4.trans.shared.b16 {%0,%1,%2,%3}, [%4];"
                 : "=r"(r[0]), "=r"(r[1]), "=r"(r[2]), "=r"(r[3]) : "r"(addr));
}
__device__ __forceinline__ void mma16816(float c[4], const u32 a[4], const u32 b[2]) {
    asm volatile("mma.sync.aligned.m16n8k16.row.col.f32.bf16.bf16.f32 "
                 "{%0,%1,%2,%3}, {%4,%5,%6,%7}, {%8,%9}, {%0,%1,%2,%3};"
                 : "+f"(c[0]), "+f"(c[1]), "+f"(c[2]), "+f"(c[3])
                 : "r"(a[0]), "r"(a[1]), "r"(a[2]), "r"(a[3]), "r"(b[0]), "r"(b[1]));
}
__device__ __forceinline__ void cp16(u32 dst, const void* src) {
    asm volatile("cp.async.cg.shared.global [%0], [%1], 16;" :: "r"(dst), "l"(src) : "memory");
}
__device__ __forceinline__ void cp_commit() {
    asm volatile("cp.async.commit_group;" ::: "memory");
}
__device__ __forceinline__ void cp_wait0() {
    asm volatile("cp.async.wait_group 0;" ::: "memory");
}
__device__ __forceinline__ __nv_bfloat162 split_hi(float v0, float v1, __nv_bfloat162& lo) {
    __nv_bfloat162 hi;
    hi.x = __float2bfloat16(v0); hi.y = __float2bfloat16(v1);
    lo.x = __float2bfloat16(v0 - __bfloat162float(hi.x));
    lo.y = __float2bfloat16(v1 - __bfloat162float(hi.y));
    return hi;
}

// ---------------- kernel 1: factored layer-1 partials + weight split/swizzle ----------------
// 106496 threads = 416 x 256: [0,40960) prep, [40960,106496) wprep
__global__ void prep_all_kernel(const float* __restrict__ emb,
                                const int*   __restrict__ edges,
                                const float* __restrict__ W1,
                                const float* __restrict__ b1,
                                const float* __restrict__ W2,
                                const float* __restrict__ W3)
{
    int idx = blockIdx.x * blockDim.x + threadIdx.x;
    if (idx < 2 * H1 * N_NODES) {
        int sec = idx >> 12;
        int r = idx & 4095;
        int k = r >> 5, s = r & 31;
        const float* w = W1 + (sec ? (32 * H1) : 0) + k;
        float acc = 0.f;
        #pragma unroll
        for (int j = 0; j < 32; j++)
            acc = fmaf(emb[s * 32 + j], w[j * H1], acc);
        (sec ? g_bT : g_aT)[k * N_NODES + s] = acc;
    } else if (idx < 40960) {
        int r = idx - 2 * H1 * N_NODES;
        int k = r >> 8, e = r & 255;
        int u = edges[2 * e], v = edges[2 * e + 1];
        const float* wu = W1 + 64 * H1 + k;
        const float* wv = W1 + 96 * H1 + k;
        float acc = b1[k];
        #pragma unroll
        for (int j = 0; j < 32; j++) {
            acc = fmaf(emb[u * 32 + j], wu[j * H1], acc);
            acc = fmaf(emb[v * 32 + j], wv[j * H1], acc);
        }
        g_cT[k * M_EDGES + e] = acc;
    } else {
        int widx = idx - 40960;                  // [0, 65536)
        int p = widx >> 13;                      // piece 0..7
        int r = widx & 8191;
        float w; u32 off;
        if ((p & 1) == 0) {
            int c = p >> 1;
            int nn = r >> 7, k = r & 127;
            w = W2[k * H2 + c * 64 + nn];
            off = (u32)(nn * 256 + k * 2) ^ (u32)((nn & 7) << 4);
        } else {
            int c = p >> 1;
            int n = r >> 6, kl = r & 63;
            w = W3[(c * 64 + kl) * H3 + n];
            off = (u32)(n * 128 + kl * 2) ^ (u32)((n & 7) << 4);
        }
        __nv_bfloat16 hi = __float2bfloat16(w);
        __nv_bfloat16 lo = __float2bfloat16(w - __bfloat162float(hi));
        *(__nv_bfloat16*)&g_Bseq[p][off] = hi;
        *(__nv_bfloat16*)&g_Bseq[p][off + 16384] = lo;
    }
}

// ================= fused MLP: persistent, 512 threads, cp.async double-buffered B =================
__device__ __forceinline__ void issue_piece(u32 dstb, int p, int tid)
{
    const char* src = (const char*)g_Bseq[p];
    #pragma unroll
    for (int i = 0; i < 4; i++) {
        int f = (tid + i * NTHREADS) * 16;
        cp16(dstb + f, src + f);
    }
    cp_commit();
}

__global__ void __launch_bounds__(NTHREADS, 1)
mlp_fused_kernel(const float* __restrict__ b2, const float* __restrict__ b3,
                 const float* __restrict__ W4, const float* __restrict__ b4)
{
    extern __shared__ unsigned char smp[];
    const u32 sb = smem_u32(smp);
    const int tid  = threadIdx.x;
    const int wid  = tid >> 5;            // 0..15
    const int lane = tid & 31;

    // l2 warp layout: 4m x 4n -> warp tile 32m x 16n (N local 64)
    const int m0_2 = (wid >> 2) * 32;
    const int n0_2 = (wid & 3) * 16;
    // l3 warp layout: 4m x 4n -> warp tile 32m x 32n (N 128)
    const int m0_3 = (wid >> 2) * 32;
    const int wn3  = wid & 3;
    const int n0_3 = wn3 * 32;

    // fragment lane constants
    const int a_krow = (lane & 7) + ((lane >> 4) << 3);     // trans-A (l2)
    const int a_cb   = ((lane >> 3) & 1) << 4;
    const int a_row  = (lane & 7) + ((lane >> 3) & 1) * 8;  // non-trans A (l3)
    const int a_kb3  = (lane >> 4) << 4;
    const int b_nrow = ((lane >> 4) << 3) + (lane & 7);     // B rows
    const int b_kb   = ((lane >> 3) & 1) << 4;
    const u32 xl     = (u32)((lane & 7) << 4);
    const u32 xk     = (u32)((a_krow & 7) << 4);

    float* red = (float*)(smp + SM_RED);
    const float b4v = __ldg(&b4[0]);
    const u32 bufs[2] = {sb + SM_B0, sb + SM_B1};

    // prefetch piece 0 into buf 0
    issue_piece(bufs[0], 0, tid);

    for (int tile = blockIdx.x; tile < NTILES; tile += GRID_MLP) {
        const int pair = tile >> 1;
        const int eb   = (tile & 1) * 128;
        const int s = pair >> 5, t = pair & 31;

        // ---- build h1 [128k][128m] hi/lo (16 warps: k = wid + 16j, m = lane*4) ----
        #pragma unroll
        for (int j = 0; j < 8; j++) {
            int k = wid + j * 16;
            float base = g_aT[k * 32 + s] + g_bT[k * 32 + t];
            u32 swz = (u32)((k & 7) << 4);
            int m = lane * 4;
            float4 c4 = *(const float4*)&g_cT[k * M_EDGES + eb + m];
            float v0 = fmaxf(base + c4.x, 0.f);
            float v1 = fmaxf(base + c4.y, 0.f);
            float v2 = fmaxf(base + c4.z, 0.f);
            float v3 = fmaxf(base + c4.w, 0.f);
            __nv_bfloat162 lp0, hp0 = split_hi(v0, v1, lp0);
            __nv_bfloat162 lp1, hp1 = split_hi(v2, v3, lp1);
            u32 off = ((u32)(k * 256 + m * 2)) ^ swz;
            *(__nv_bfloat162*)(smp + SM_A1H + off)     = hp0;
            *(__nv_bfloat162*)(smp + SM_A1H + off + 4) = hp1;
            *(__nv_bfloat162*)(smp + SM_A1L + off)     = lp0;
            *(__nv_bfloat162*)(smp + SM_A1L + off + 4) = lp1;
        }
        cp_wait0();
        __syncthreads();            // A1 + piece0 ready

        float acc3[2][4][4];
        #pragma unroll
        for (int mt = 0; mt < 2; mt++)
            #pragma unroll
            for (int nt = 0; nt < 4; nt++)
                #pragma unroll
                for (int i = 0; i < 4; i++) acc3[mt][nt][i] = 0.f;

        #pragma unroll 1
        for (int c = 0; c < 4; c++) {
            const u32 bb2 = bufs[0];       // even pieces -> buf0
            const u32 bb3 = bufs[1];       // odd pieces -> buf1

            // prefetch B3 sub c
            issue_piece(bb3, 2 * c + 1, tid);

            // ---- L2 sub-MMA: acc2 = h1 x B2[:, c*64 .. c*64+64) ----
            float acc2[2][2][4];
            #pragma unroll
            for (int mt = 0; mt < 2; mt++)
                #pragma unroll
                for (int nt = 0; nt < 2; nt++)
                    #pragma unroll
                    for (int i = 0; i < 4; i++) acc2[mt][nt][i] = 0.f;

            #pragma unroll
            for (int ks = 0; ks < 8; ks++) {
                u32 ah[2][4], al[2][4];
                #pragma unroll
                for (int mt = 0; mt < 2; mt++) {
                    u32 off = ((u32)((ks * 16 + a_krow) * 256 + (m0_2 + mt * 16) * 2 + a_cb)) ^ xk;
                    ldm_x4_t(ah[mt], sb + SM_A1H + off);
                    ldm_x4_t(al[mt], sb + SM_A1L + off);
                }
                u32 bh[4], bl[4];
                {
                    u32 off = ((u32)((n0_2 + b_nrow) * 256 + ks * 32 + b_kb)) ^ xl;
                    ldm_x4(bh, bb2 + off);
                    ldm_x4(bl, bb2 + 16384 + off);
                }
                #pragma unroll
                for (int mt = 0; mt < 2; mt++)
                    #pragma unroll
                    for (int nt = 0; nt < 2; nt++) {
                        const u32* Bh = &bh[nt * 2];
                        const u32* Bl = &bl[nt * 2];
                        mma16816(acc2[mt][nt], ah[mt], Bh);
                        mma16816(acc2[mt][nt], ah[mt], Bl);
                        mma16816(acc2[mt][nt], al[mt], Bh);
                    }
            }

            // ---- h2 epilogue -> A2 [128m][64k] ----
            #pragma unroll
            for (int nt = 0; nt < 2; nt++) {
                int nl = n0_2 + nt * 8 + (lane & 3) * 2;
                int gc = c * 64 + nl;
                float bx = __ldg(&b2[gc]), by = __ldg(&b2[gc + 1]);
                #pragma unroll
                for (int mt = 0; mt < 2; mt++) {
                    #pragma unroll
                    for (int h = 0; h < 2; h++) {
                        int row = m0_2 + mt * 16 + (lane >> 2) + h * 8;
                        float v0 = fmaxf(acc2[mt][nt][h * 2 + 0] + bx, 0.f);
                        float v1 = fmaxf(acc2[mt][nt][h * 2 + 1] + by, 0.f);
                        __nv_bfloat162 lp, hp = split_hi(v0, v1, lp);
                        u32 off = ((u32)(row * 128 + nl * 2)) ^ (u32)((row & 7) << 4);
                        *(__nv_bfloat162*)(smp + SM_A2H + off) = hp;
                        *(__nv_bfloat162*)(smp + SM_A2L + off) = lp;
                    }
                }
            }
            cp_wait0();
            __syncthreads();        // A2 visible + B3 piece ready

            // prefetch next even piece (wraps to 0 for next tile)
            issue_piece(bb2, (2 * c + 2) & 7, tid);

            // ---- L3 sub-MMA: acc3 += h2c x B3[c*64.., :] ----
            #pragma unroll
            for (int ks = 0; ks < 4; ks++) {
                u32 ah[2][4], al[2][4];
                #pragma unroll
                for (int mt = 0; mt < 2; mt++) {
                    u32 off = ((u32)((m0_3 + mt * 16 + a_row) * 128 + ks * 32 + a_kb3)) ^ xl;
                    ldm_x4(ah[mt], sb + SM_A2H + off);
                    ldm_x4(al[mt], sb + SM_A2L + off);
                }
                u32 bh[2][4], bl[2][4];
                #pragma unroll
                for (int np = 0; np < 2; np++) {
                    u32 off = ((u32)((n0_3 + np * 16 + b_nrow) * 128 + ks * 32 + b_kb)) ^ xl;
                    ldm_x4(bh[np], bb3 + off);
                    ldm_x4(bl[np], bb3 + 16384 + off);
                }
                #pragma unroll
                for (int mt = 0; mt < 2; mt++)
                    #pragma unroll
                    for (int nt = 0; nt < 4; nt++) {
                        const u32* Bh = &bh[nt >> 1][(nt & 1) * 2];
                        const u32* Bl = &bl[nt >> 1][(nt & 1) * 2];
                        mma16816(acc3[mt][nt], ah[mt], Bh);
                        mma16816(acc3[mt][nt], ah[mt], Bl);
                        mma16816(acc3[mt][nt], al[mt], Bh);
                    }
            }
            cp_wait0();
            __syncthreads();        // A2 free for next epilogue + next B2 ready
        }

        // ---- layer 4: pred = relu(h3 + b3) . W4 + b4 ----
        #pragma unroll
        for (int mt = 0; mt < 2; mt++) {
            #pragma unroll
            for (int h = 0; h < 2; h++) {
                float part = 0.f;
                #pragma unroll
                for (int nt = 0; nt < 4; nt++) {
                    int cc = n0_3 + nt * 8 + (lane & 3) * 2;
                    float h0 = fmaxf(acc3[mt][nt][h * 2 + 0] + __ldg(&b3[cc]), 0.f);
                    float h1 = fmaxf(acc3[mt][nt][h * 2 + 1] + __ldg(&b3[cc + 1]), 0.f);
                    part = fmaf(h0, __ldg(&W4[cc]), part);
                    part = fmaf(h1, __ldg(&W4[cc + 1]), part);
                }
                part += __shfl_xor_sync(0xffffffffu, part, 1);
                part += __shfl_xor_sync(0xffffffffu, part, 2);
                if ((lane & 3) == 0) {
                    int row = m0_3 + mt * 16 + (lane >> 2) + h * 8;
                    red[wn3 * 128 + row] = part;
                }
            }
        }
        __syncthreads();
        if (tid < 128) {
            float acc = red[tid] + red[128 + tid] + red[256 + tid] + red[384 + tid];
            g_preds[pair * M_EDGES + eb + tid] = acc + b4v;
        }
        __syncthreads();            // red consumed before next tile reuses smem
    }
    cp_wait0();
}

// ---------------- kernel 3: fused scatter + 50-step power iteration ----------------
// grid 128 x 256: one warp per (s,t) pair; warp-private 32x32 routing matrix in smem
__global__ void power_kernel(const int* __restrict__ edges)
{
    __shared__ float As[8][1024];
    const int wid  = threadIdx.x >> 5;
    const int lane = threadIdx.x & 31;
    const int p    = blockIdx.x * 8 + wid;
    float* A = As[wid];

    #pragma unroll
    for (int i = lane; i < 1024; i += 32) A[i] = 0.f;
    __syncwarp();

    #pragma unroll
    for (int j = 0; j < 8; j++) {
        int e = j * 32 + lane;
        int u = edges[2 * e], v = edges[2 * e + 1];
        atomicAdd(&A[u * 32 + v], g_preds[p * M_EDGES + e]);
    }
    __syncwarp();

    const int s = p >> 5, t = p & 31;
    if (lane == 0) A[s * 32 + s] += 1.f;
    __syncwarp();

    float col[32];                       // A[:, lane]
    #pragma unroll
    for (int u = 0; u < 32; u++) col[u] = A[u * 32 + lane];

    float x = 1.0f / 32.0f;
    for (int it = 0; it < 50; it++) {
        float a0 = 0.f, a1 = 0.f, a2 = 0.f, a3 = 0.f;
        #pragma unroll
        for (int u = 0; u < 32; u += 4) {
            a0 = fmaf(__shfl_sync(0xffffffffu, x, u),     col[u],     a0);
            a1 = fmaf(__shfl_sync(0xffffffffu, x, u + 1), col[u + 1], a1);
            a2 = fmaf(__shfl_sync(0xffffffffu, x, u + 2), col[u + 2], a2);
            a3 = fmaf(__shfl_sync(0xffffffffu, x, u + 3), col[u + 3], a3);
        }
        float acc = (a0 + a1) + (a2 + a3);
        float ss = acc * acc;
        #pragma unroll
        for (int o = 16; o > 0; o >>= 1)
            ss += __shfl_xor_sync(0xffffffffu, ss, o);
        x = acc / (sqrtf(ss) + EPSF);
    }
    float xs = __shfl_sync(0xffffffffu, x, s);
    float d = (s != t) ? x / (xs + EPSF) : 0.f;
    g_delta[p * 32 + lane] = d;
}

// ---------------- kernel 4: deterministic reduction + normalize ----------------
__global__ void reduce_kernel(float* __restrict__ out)
{
    __shared__ float red[32][33];
    int v = threadIdx.x, g = threadIdx.y;
    float acc = 0.f;
    #pragma unroll 4
    for (int p = g; p < NPAIR; p += 32) acc += g_delta[p * 32 + v];
    red[g][v] = acc;
    __syncthreads();
    #pragma unroll
    for (int st = 16; st > 0; st >>= 1) {
        if (g < st) red[g][v] += red[g + st][v];
        __syncthreads();
    }
    if (g == 0) {
        float r = red[0][v];
        float tot = r;
        #pragma unroll
        for (int o = 16; o > 0; o >>= 1)
            tot += __shfl_xor_sync(0xffffffffu, tot, o);
        out[v] = r / tot;
    }
}

// ---------------- launch ----------------
extern "C" void kernel_launch(void* const* d_in, const int* in_sizes, int n_in,
                              void* d_out, int out_size)
{
    (void)in_sizes; (void)n_in; (void)out_size;
    const float* emb   = (const float*)d_in[1];
    const int*   edges = (const int*)  d_in[2];
    const float* W1 = (const float*)d_in[3];
    const float* b1 = (const float*)d_in[4];
    const float* W2 = (const float*)d_in[5];
    const float* b2 = (const float*)d_in[6];
    const float* W3 = (const float*)d_in[7];
    const float* b3 = (const float*)d_in[8];
    const float* W4 = (const float*)d_in[9];
    const float* b4 = (const float*)d_in[10];
    float* out = (float*)d_out;

    static int attr_set = 0;
    if (!attr_set) {
        cudaFuncSetAttribute(mlp_fused_kernel, cudaFuncAttributeMaxDynamicSharedMemorySize, SM_TOTAL);
        attr_set = 1;
    }

    prep_all_kernel <<<416, 256>>>(emb, edges, W1, b1, W2, W3);
    mlp_fused_kernel<<<GRID_MLP, NTHREADS, SM_TOTAL>>>(b2, b3, W4, b4);
    power_kernel    <<<128, 256>>>(edges);
    reduce_kernel   <<<1, dim3(32, 32)>>>(out);
}

// round 12
// speedup vs baseline: 2.0301x; 1.0238x over previous
#include <cuda_runtime.h>
#include <cuda_bf16.h>
#include <cstdint>

#define N_NODES 32
#define M_EDGES 256
#define H1 128
#define H2 256
#define H3 128
#define NPAIR 1024
#define EPSF 1e-9f
#define NTILES 2048          // pair * 2 halves of 128 edge-rows
#define GRID_MLP 152
#define NTHREADS 512

typedef uint32_t u32;

// ---------------- scratch (no allocations allowed) ----------------
__device__ float g_aT[H1 * N_NODES];
__device__ float g_bT[H1 * N_NODES];
__device__ float g_cT[H1 * M_EDGES];
__device__ float g_preds4[4][NPAIR * M_EDGES];   // per-warp-column partial preds
__device__ float g_delta[NPAIR * N_NODES];
__device__ float g_part[8][N_NODES];             // reduce stage-1 partials
// 8 cyclic pre-swizzled weight pieces, 32KB each: [hi 16KB | lo 16KB]
__device__ __align__(16) unsigned char g_Bseq[8][32768];

// ---------------- smem layout (bytes) ----------------
#define SM_A1H 0                       // h1 hi, [128k][128m], 256B rows, 32KB
#define SM_A1L 32768                   // h1 lo
#define SM_A2H 65536                   // h2 sub hi, [128m][64k], 128B rows, 16KB
#define SM_A2L 81920                   // h2 sub lo
#define SM_B0  98304                   // B ring buf 0 (32KB)
#define SM_B1  131072                  // B ring buf 1 (32KB)
#define SM_TOTAL 163840

// ---------------- PTX helpers ----------------
__device__ __forceinline__ u32 smem_u32(const void* p) {
    u32 a; asm("{ .reg .u64 t; cvta.to.shared.u64 t, %1; cvt.u32.u64 %0, t; }" : "=r"(a) : "l"(p));
    return a;
}
__device__ __forceinline__ void ldm_x4(u32 r[4], u32 addr) {
    asm volatile("ldmatrix.sync.aligned.m8n8.x4.shared.b16 {%0,%1,%2,%3}, [%4];"
                 : "=r"(r[0]), "=r"(r[1]), "=r"(r[2]), "=r"(r[3]) : "r"(addr));
}
__device__ __forceinline__ void ldm_x4_t(u32 r[4], u32 addr) {
    asm volatile("ldmatrix.sync.aligned.m8n8.x4.trans.shared.b16 {%0,%1,%2,%3}, [%4];"
                 : "=r"(r[0]), "=r"(r[1]), "=r"(r[2]), "=r"(r[3]) : "r"(addr));
}
__device__ __forceinline__ void mma16816(float c[4], const u32 a[4], const u32 b[2]) {
    asm volatile("mma.sync.aligned.m16n8k16.row.col.f32.bf16.bf16.f32 "
                 "{%0,%1,%2,%3}, {%4,%5,%6,%7}, {%8,%9}, {%0,%1,%2,%3};"
                 : "+f"(c[0]), "+f"(c[1]), "+f"(c[2]), "+f"(c[3])
                 : "r"(a[0]), "r"(a[1]), "r"(a[2]), "r"(a[3]), "r"(b[0]), "r"(b[1]));
}
__device__ __forceinline__ void cp16(u32 dst, const void* src) {
    asm volatile("cp.async.cg.shared.global [%0], [%1], 16;" :: "r"(dst), "l"(src) : "memory");
}
__device__ __forceinline__ void cp_commit() {
    asm volatile("cp.async.commit_group;" ::: "memory");
}
__device__ __forceinline__ void cp_wait0() {
    asm volatile("cp.async.wait_group 0;" ::: "memory");
}
__device__ __forceinline__ __nv_bfloat162 split_hi(float v0, float v1, __nv_bfloat162& lo) {
    __nv_bfloat162 hi;
    hi.x = __float2bfloat16(v0); hi.y = __float2bfloat16(v1);
    lo.x = __float2bfloat16(v0 - __bfloat162float(hi.x));
    lo.y = __float2bfloat16(v1 - __bfloat162float(hi.y));
    return hi;
}

// ---------------- kernel 1: factored layer-1 partials + weight split/swizzle ----------------
// 106496 threads = 416 x 256: [0,40960) prep, [40960,106496) wprep
__global__ void prep_all_kernel(const float* __restrict__ emb,
                                const int*   __restrict__ edges,
                                const float* __restrict__ W1,
                                const float* __restrict__ b1,
                                const float* __restrict__ W2,
                                const float* __restrict__ W3)
{
    int idx = blockIdx.x * blockDim.x + threadIdx.x;
    if (idx < 2 * H1 * N_NODES) {
        int sec = idx >> 12;
        int r = idx & 4095;
        int k = r >> 5, s = r & 31;
        const float* w = W1 + (sec ? (32 * H1) : 0) + k;
        float acc = 0.f;
        #pragma unroll
        for (int j = 0; j < 32; j++)
            acc = fmaf(emb[s * 32 + j], w[j * H1], acc);
        (sec ? g_bT : g_aT)[k * N_NODES + s] = acc;
    } else if (idx < 40960) {
        int r = idx - 2 * H1 * N_NODES;
        int k = r >> 8, e = r & 255;
        int u = edges[2 * e], v = edges[2 * e + 1];
        const float* wu = W1 + 64 * H1 + k;
        const float* wv = W1 + 96 * H1 + k;
        float acc = b1[k];
        #pragma unroll
        for (int j = 0; j < 32; j++) {
            acc = fmaf(emb[u * 32 + j], wu[j * H1], acc);
            acc = fmaf(emb[v * 32 + j], wv[j * H1], acc);
        }
        g_cT[k * M_EDGES + e] = acc;
    } else {
        int widx = idx - 40960;                  // [0, 65536)
        int p = widx >> 13;                      // piece 0..7
        int r = widx & 8191;
        float w; u32 off;
        if ((p & 1) == 0) {
            int c = p >> 1;
            int nn = r >> 7, k = r & 127;
            w = W2[k * H2 + c * 64 + nn];
            off = (u32)(nn * 256 + k * 2) ^ (u32)((nn & 7) << 4);
        } else {
            int c = p >> 1;
            int n = r >> 6, kl = r & 63;
            w = W3[(c * 64 + kl) * H3 + n];
            off = (u32)(n * 128 + kl * 2) ^ (u32)((n & 7) << 4);
        }
        __nv_bfloat16 hi = __float2bfloat16(w);
        __nv_bfloat16 lo = __float2bfloat16(w - __bfloat162float(hi));
        *(__nv_bfloat16*)&g_Bseq[p][off] = hi;
        *(__nv_bfloat16*)&g_Bseq[p][off + 16384] = lo;
    }
}

// ================= fused MLP: persistent, 512 threads, cp.async double-buffered B =================
__device__ __forceinline__ void issue_piece(u32 dstb, int p, int tid)
{
    const char* src = (const char*)g_Bseq[p];
    #pragma unroll
    for (int i = 0; i < 4; i++) {
        int f = (tid + i * NTHREADS) * 16;
        cp16(dstb + f, src + f);
    }
    cp_commit();
}

__global__ void __launch_bounds__(NTHREADS, 1)
mlp_fused_kernel(const float* __restrict__ b2, const float* __restrict__ b3,
                 const float* __restrict__ W4)
{
    extern __shared__ unsigned char smp[];
    const u32 sb = smem_u32(smp);
    const int tid  = threadIdx.x;
    const int wid  = tid >> 5;            // 0..15
    const int lane = tid & 31;

    // l2 warp layout: 4m x 4n -> warp tile 32m x 16n (N local 64)
    const int m0_2 = (wid >> 2) * 32;
    const int n0_2 = (wid & 3) * 16;
    // l3 warp layout: 4m x 4n -> warp tile 32m x 32n (N 128)
    const int m0_3 = (wid >> 2) * 32;
    const int wn3  = wid & 3;
    const int n0_3 = wn3 * 32;

    // fragment lane constants
    const int a_krow = (lane & 7) + ((lane >> 4) << 3);     // trans-A (l2)
    const int a_cb   = ((lane >> 3) & 1) << 4;
    const int a_row  = (lane & 7) + ((lane >> 3) & 1) * 8;  // non-trans A (l3)
    const int a_kb3  = (lane >> 4) << 4;
    const int b_nrow = ((lane >> 4) << 3) + (lane & 7);     // B rows
    const int b_kb   = ((lane >> 3) & 1) << 4;
    const u32 xl     = (u32)((lane & 7) << 4);
    const u32 xk     = (u32)((a_krow & 7) << 4);

    const u32 bufs[2] = {sb + SM_B0, sb + SM_B1};

    // prefetch piece 0 into buf 0
    issue_piece(bufs[0], 0, tid);

    for (int tile = blockIdx.x; tile < NTILES; tile += GRID_MLP) {
        const int pair = tile >> 1;
        const int eb   = (tile & 1) * 128;
        const int s = pair >> 5, t = pair & 31;

        // ---- build h1 [128k][128m] hi/lo (16 warps: k = wid + 16j, m = lane*4) ----
        #pragma unroll
        for (int j = 0; j < 8; j++) {
            int k = wid + j * 16;
            float base = g_aT[k * 32 + s] + g_bT[k * 32 + t];
            u32 swz = (u32)((k & 7) << 4);
            int m = lane * 4;
            float4 c4 = *(const float4*)&g_cT[k * M_EDGES + eb + m];
            float v0 = fmaxf(base + c4.x, 0.f);
            float v1 = fmaxf(base + c4.y, 0.f);
            float v2 = fmaxf(base + c4.z, 0.f);
            float v3 = fmaxf(base + c4.w, 0.f);
            __nv_bfloat162 lp0, hp0 = split_hi(v0, v1, lp0);
            __nv_bfloat162 lp1, hp1 = split_hi(v2, v3, lp1);
            u32 off = ((u32)(k * 256 + m * 2)) ^ swz;
            *(__nv_bfloat162*)(smp + SM_A1H + off)     = hp0;
            *(__nv_bfloat162*)(smp + SM_A1H + off + 4) = hp1;
            *(__nv_bfloat162*)(smp + SM_A1L + off)     = lp0;
            *(__nv_bfloat162*)(smp + SM_A1L + off + 4) = lp1;
        }
        cp_wait0();
        __syncthreads();            // A1 ready + prefetched B2 piece 0 visible
                                    // (also guards A2 reuse vs prev tile's last L3)

        float acc3[2][4][4];
        #pragma unroll
        for (int mt = 0; mt < 2; mt++)
            #pragma unroll
            for (int nt = 0; nt < 4; nt++)
                #pragma unroll
                for (int i = 0; i < 4; i++) acc3[mt][nt][i] = 0.f;

        #pragma unroll 1
        for (int c = 0; c < 4; c++) {
            const u32 bb2 = bufs[0];       // even pieces -> buf0
            const u32 bb3 = bufs[1];       // odd pieces -> buf1

            // prefetch B3 sub c
            issue_piece(bb3, 2 * c + 1, tid);

            // ---- L2 sub-MMA: acc2 = h1 x B2[:, c*64 .. c*64+64) ----
            float acc2[2][2][4];
            #pragma unroll
            for (int mt = 0; mt < 2; mt++)
                #pragma unroll
                for (int nt = 0; nt < 2; nt++)
                    #pragma unroll
                    for (int i = 0; i < 4; i++) acc2[mt][nt][i] = 0.f;

            #pragma unroll
            for (int ks = 0; ks < 8; ks++) {
                u32 ah[2][4], al[2][4];
                #pragma unroll
                for (int mt = 0; mt < 2; mt++) {
                    u32 off = ((u32)((ks * 16 + a_krow) * 256 + (m0_2 + mt * 16) * 2 + a_cb)) ^ xk;
                    ldm_x4_t(ah[mt], sb + SM_A1H + off);
                    ldm_x4_t(al[mt], sb + SM_A1L + off);
                }
                u32 bh[4], bl[4];
                {
                    u32 off = ((u32)((n0_2 + b_nrow) * 256 + ks * 32 + b_kb)) ^ xl;
                    ldm_x4(bh, bb2 + off);
                    ldm_x4(bl, bb2 + 16384 + off);
                }
                #pragma unroll
                for (int mt = 0; mt < 2; mt++)
                    #pragma unroll
                    for (int nt = 0; nt < 2; nt++) {
                        const u32* Bh = &bh[nt * 2];
                        const u32* Bl = &bl[nt * 2];
                        mma16816(acc2[mt][nt], ah[mt], Bh);
                        mma16816(acc2[mt][nt], ah[mt], Bl);
                        mma16816(acc2[mt][nt], al[mt], Bh);
                    }
            }

            // ---- h2 epilogue -> A2 [128m][64k] ----
            #pragma unroll
            for (int nt = 0; nt < 2; nt++) {
                int nl = n0_2 + nt * 8 + (lane & 3) * 2;
                int gc = c * 64 + nl;
                float bx = __ldg(&b2[gc]), by = __ldg(&b2[gc + 1]);
                #pragma unroll
                for (int mt = 0; mt < 2; mt++) {
                    #pragma unroll
                    for (int h = 0; h < 2; h++) {
                        int row = m0_2 + mt * 16 + (lane >> 2) + h * 8;
                        float v0 = fmaxf(acc2[mt][nt][h * 2 + 0] + bx, 0.f);
                        float v1 = fmaxf(acc2[mt][nt][h * 2 + 1] + by, 0.f);
                        __nv_bfloat162 lp, hp = split_hi(v0, v1, lp);
                        u32 off = ((u32)(row * 128 + nl * 2)) ^ (u32)((row & 7) << 4);
                        *(__nv_bfloat162*)(smp + SM_A2H + off) = hp;
                        *(__nv_bfloat162*)(smp + SM_A2L + off) = lp;
                    }
                }
            }
            cp_wait0();
            __syncthreads();        // A2 visible + B3 piece ready

            // prefetch next even piece (wraps to 0 for next tile)
            issue_piece(bb2, (2 * c + 2) & 7, tid);

            // ---- L3 sub-MMA: acc3 += h2c x B3[c*64.., :] ----
            #pragma unroll
            for (int ks = 0; ks < 4; ks++) {
                u32 ah[2][4], al[2][4];
                #pragma unroll
                for (int mt = 0; mt < 2; mt++) {
                    u32 off = ((u32)((m0_3 + mt * 16 + a_row) * 128 + ks * 32 + a_kb3)) ^ xl;
                    ldm_x4(ah[mt], sb + SM_A2H + off);
                    ldm_x4(al[mt], sb + SM_A2L + off);
                }
                u32 bh[2][4], bl[2][4];
                #pragma unroll
                for (int np = 0; np < 2; np++) {
                    u32 off = ((u32)((n0_3 + np * 16 + b_nrow) * 128 + ks * 32 + b_kb)) ^ xl;
                    ldm_x4(bh[np], bb3 + off);
                    ldm_x4(bl[np], bb3 + 16384 + off);
                }
                #pragma unroll
                for (int mt = 0; mt < 2; mt++)
                    #pragma unroll
                    for (int nt = 0; nt < 4; nt++) {
                        const u32* Bh = &bh[nt >> 1][(nt & 1) * 2];
                        const u32* Bl = &bl[nt >> 1][(nt & 1) * 2];
                        mma16816(acc3[mt][nt], ah[mt], Bh);
                        mma16816(acc3[mt][nt], ah[mt], Bl);
                        mma16816(acc3[mt][nt], al[mt], Bh);
                    }
            }
            if (c < 3) {            // last chunk: covered by next tile's post-h1 barrier
                cp_wait0();
                __syncthreads();    // A2 free for next epilogue + next B2 ready
            }
        }

        // ---- layer 4: partial pred per warp-column -> g_preds4 (no barriers) ----
        #pragma unroll
        for (int mt = 0; mt < 2; mt++) {
            #pragma unroll
            for (int h = 0; h < 2; h++) {
                float part = 0.f;
                #pragma unroll
                for (int nt = 0; nt < 4; nt++) {
                    int cc = n0_3 + nt * 8 + (lane & 3) * 2;
                    float h0 = fmaxf(acc3[mt][nt][h * 2 + 0] + __ldg(&b3[cc]), 0.f);
                    float h1 = fmaxf(acc3[mt][nt][h * 2 + 1] + __ldg(&b3[cc + 1]), 0.f);
                    part = fmaf(h0, __ldg(&W4[cc]), part);
                    part = fmaf(h1, __ldg(&W4[cc + 1]), part);
                }
                part += __shfl_xor_sync(0xffffffffu, part, 1);
                part += __shfl_xor_sync(0xffffffffu, part, 2);
                if ((lane & 3) == 0) {
                    int row = m0_3 + mt * 16 + (lane >> 2) + h * 8;
                    g_preds4[wn3][pair * M_EDGES + eb + row] = part;
                }
            }
        }
    }
    cp_wait0();
}

// ---------------- kernel 3: fused partial-sum + scatter + 50-step power iteration ----------------
// grid 128 x 256: one warp per (s,t) pair; warp-private 32x32 routing matrix in smem
__global__ void power_kernel(const int* __restrict__ edges, const float* __restrict__ b4)
{
    __shared__ float As[8][1024];
    const int wid  = threadIdx.x >> 5;
    const int lane = threadIdx.x & 31;
    const int p    = blockIdx.x * 8 + wid;
    float* A = As[wid];
    const float b4v = __ldg(&b4[0]);

    #pragma unroll
    for (int i = lane; i < 1024; i += 32) A[i] = 0.f;
    __syncwarp();

    #pragma unroll
    for (int j = 0; j < 8; j++) {
        int e = j * 32 + lane;
        int base = p * M_EDGES + e;
        float pred = ((g_preds4[0][base] + g_preds4[1][base])
                    + (g_preds4[2][base] + g_preds4[3][base])) + b4v;
        int u = edges[2 * e], v = edges[2 * e + 1];
        atomicAdd(&A[u * 32 + v], pred);
    }
    __syncwarp();

    const int s = p >> 5, t = p & 31;
    if (lane == 0) A[s * 32 + s] += 1.f;
    __syncwarp();

    float col[32];                       // A[:, lane]
    #pragma unroll
    for (int u = 0; u < 32; u++) col[u] = A[u * 32 + lane];

    float x = 1.0f / 32.0f;
    for (int it = 0; it < 50; it++) {
        float a0 = 0.f, a1 = 0.f, a2 = 0.f, a3 = 0.f;
        #pragma unroll
        for (int u = 0; u < 32; u += 4) {
            a0 = fmaf(__shfl_sync(0xffffffffu, x, u),     col[u],     a0);
            a1 = fmaf(__shfl_sync(0xffffffffu, x, u + 1), col[u + 1], a1);
            a2 = fmaf(__shfl_sync(0xffffffffu, x, u + 2), col[u + 2], a2);
            a3 = fmaf(__shfl_sync(0xffffffffu, x, u + 3), col[u + 3], a3);
        }
        float acc = (a0 + a1) + (a2 + a3);
        float ss = acc * acc;
        #pragma unroll
        for (int o = 16; o > 0; o >>= 1)
            ss += __shfl_xor_sync(0xffffffffu, ss, o);
        x = acc / (sqrtf(ss) + EPSF);
    }
    float xs = __shfl_sync(0xffffffffu, x, s);
    float d = (s != t) ? x / (xs + EPSF) : 0.f;
    g_delta[p * 32 + lane] = d;
}

// ---------------- kernel 4a: stage-1 reduction (8 CTAs, deterministic) ----------------
__global__ void reduce1_kernel()
{
    __shared__ float red[8][33];
    int v = threadIdx.x & 31, g = threadIdx.x >> 5;   // 256 threads: 8 groups
    float acc = 0.f;
    #pragma unroll
    for (int j = 0; j < 16; j++) {
        int p = blockIdx.x * 128 + g + j * 8;
        acc += g_delta[p * 32 + v];
    }
    red[g][v] = acc;
    __syncthreads();
    #pragma unroll
    for (int st = 4; st > 0; st >>= 1) {
        if (g < st) red[g][v] += red[g + st][v];
        __syncthreads();
    }
    if (g == 0) g_part[blockIdx.x][v] = red[0][v];
}

// ---------------- kernel 4b: finalize + normalize (1 warp) ----------------
__global__ void reduce2_kernel(float* __restrict__ out)
{
    int v = threadIdx.x;
    float r = 0.f;
    #pragma unroll
    for (int b = 0; b < 8; b++) r += g_part[b][v];
    float tot = r;
    #pragma unroll
    for (int o = 16; o > 0; o >>= 1)
        tot += __shfl_xor_sync(0xffffffffu, tot, o);
    out[v] = r / tot;
}

// ---------------- launch ----------------
extern "C" void kernel_launch(void* const* d_in, const int* in_sizes, int n_in,
                              void* d_out, int out_size)
{
    (void)in_sizes; (void)n_in; (void)out_size;
    const float* emb   = (const float*)d_in[1];
    const int*   edges = (const int*)  d_in[2];
    const float* W1 = (const float*)d_in[3];
    const float* b1 = (const float*)d_in[4];
    const float* W2 = (const float*)d_in[5];
    const float* b2 = (const float*)d_in[6];
    const float* W3 = (const float*)d_in[7];
    const float* b3 = (const float*)d_in[8];
    const float* W4 = (const float*)d_in[9];
    const float* b4 = (const float*)d_in[10];
    float* out = (float*)d_out;

    static int attr_set = 0;
    if (!attr_set) {
        cudaFuncSetAttribute(mlp_fused_kernel, cudaFuncAttributeMaxDynamicSharedMemorySize, SM_TOTAL);
        attr_set = 1;
    }

    prep_all_kernel <<<416, 256>>>(emb, edges, W1, b1, W2, W3);
    mlp_fused_kernel<<<GRID_MLP, NTHREADS, SM_TOTAL>>>(b2, b3, W4);
    power_kernel    <<<128, 256>>>(edges, b4);
    reduce1_kernel  <<<8, 256>>>();
    reduce2_kernel  <<<1, 32>>>(out);
}

// round 13
// speedup vs baseline: 2.0408x; 1.0053x over previous
#include <cuda_runtime.h>
#include <cuda_bf16.h>
#include <cstdint>

#define N_NODES 32
#define M_EDGES 256
#define H1 128
#define H2 256
#define H3 128
#define NPAIR 1024
#define EPSF 1e-9f
#define NTILES 2048          // pair * 2 halves of 128 edge-rows
#define GRID_MLP 152
#define NTHREADS 512

typedef uint32_t u32;

// ---------------- scratch (no allocations allowed) ----------------
__device__ float g_aT[H1 * N_NODES];
__device__ float g_bT[H1 * N_NODES];
__device__ float g_cT[H1 * M_EDGES];
__device__ float g_preds4[4][NPAIR * M_EDGES];   // per-warp-column partial preds
__device__ float g_delta[NPAIR * N_NODES];
__device__ int   g_ctr;                          // last-block-done counter
// 8 cyclic pre-swizzled weight pieces, 32KB each: [hi 16KB | lo 16KB]
__device__ __align__(16) unsigned char g_Bseq[8][32768];

// ---------------- smem layout (bytes) ----------------
#define SM_A1H 0                       // h1 hi, [128k][128m], 256B rows, 32KB
#define SM_A1L 32768                   // h1 lo
#define SM_A2H 65536                   // h2 sub hi, [128m][64k], 128B rows, 16KB
#define SM_A2L 81920                   // h2 sub lo
#define SM_B0  98304                   // B ring buf 0 (32KB)
#define SM_B1  131072                  // B ring buf 1 (32KB)
#define SM_TOTAL 163840

// ---------------- PTX helpers ----------------
__device__ __forceinline__ u32 smem_u32(const void* p) {
    u32 a; asm("{ .reg .u64 t; cvta.to.shared.u64 t, %1; cvt.u32.u64 %0, t; }" : "=r"(a) : "l"(p));
    return a;
}
__device__ __forceinline__ void ldm_x4(u32 r[4], u32 addr) {
    asm volatile("ldmatrix.sync.aligned.m8n8.x4.shared.b16 {%0,%1,%2,%3}, [%4];"
                 : "=r"(r[0]), "=r"(r[1]), "=r"(r[2]), "=r"(r[3]) : "r"(addr));
}
__device__ __forceinline__ void ldm_x4_t(u32 r[4], u32 addr) {
    asm volatile("ldmatrix.sync.aligned.m8n8.x4.trans.shared.b16 {%0,%1,%2,%3}, [%4];"
                 : "=r"(r[0]), "=r"(r[1]), "=r"(r[2]), "=r"(r[3]) : "r"(addr));
}
__device__ __forceinline__ void mma16816(float c[4], const u32 a[4], const u32 b[2]) {
    asm volatile("mma.sync.aligned.m16n8k16.row.col.f32.bf16.bf16.f32 "
                 "{%0,%1,%2,%3}, {%4,%5,%6,%7}, {%8,%9}, {%0,%1,%2,%3};"
                 : "+f"(c[0]), "+f"(c[1]), "+f"(c[2]), "+f"(c[3])
                 : "r"(a[0]), "r"(a[1]), "r"(a[2]), "r"(a[3]), "r"(b[0]), "r"(b[1]));
}
__device__ __forceinline__ void cp16(u32 dst, const void* src) {
    asm volatile("cp.async.cg.shared.global [%0], [%1], 16;" :: "r"(dst), "l"(src) : "memory");
}
__device__ __forceinline__ void cp_commit() {
    asm volatile("cp.async.commit_group;" ::: "memory");
}
__device__ __forceinline__ void cp_wait0() {
    asm volatile("cp.async.wait_group 0;" ::: "memory");
}
__device__ __forceinline__ __nv_bfloat162 split_hi(float v0, float v1, __nv_bfloat162& lo) {
    __nv_bfloat162 hi;
    hi.x = __float2bfloat16(v0); hi.y = __float2bfloat16(v1);
    lo.x = __float2bfloat16(v0 - __bfloat162float(hi.x));
    lo.y = __float2bfloat16(v1 - __bfloat162float(hi.y));
    return hi;
}

// ---------------- kernel 1: factored layer-1 partials + weight split/swizzle ----------------
// 106496 threads = 416 x 256: [0,40960) prep, [40960,106496) wprep
__global__ void prep_all_kernel(const float* __restrict__ emb,
                                const int*   __restrict__ edges,
                                const float* __restrict__ W1,
                                const float* __restrict__ b1,
                                const float* __restrict__ W2,
                                const float* __restrict__ W3)
{
    int idx = blockIdx.x * blockDim.x + threadIdx.x;
    if (idx == 0) g_ctr = 0;                     // reset last-block counter (deterministic per replay)
    if (idx < 2 * H1 * N_NODES) {
        int sec = idx >> 12;
        int r = idx & 4095;
        int k = r >> 5, s = r & 31;
        const float* w = W1 + (sec ? (32 * H1) : 0) + k;
        float acc = 0.f;
        #pragma unroll
        for (int j = 0; j < 32; j++)
            acc = fmaf(emb[s * 32 + j], w[j * H1], acc);
        (sec ? g_bT : g_aT)[k * N_NODES + s] = acc;
    } else if (idx < 40960) {
        int r = idx - 2 * H1 * N_NODES;
        int k = r >> 8, e = r & 255;
        int u = edges[2 * e], v = edges[2 * e + 1];
        const float* wu = W1 + 64 * H1 + k;
        const float* wv = W1 + 96 * H1 + k;
        float acc = b1[k];
        #pragma unroll
        for (int j = 0; j < 32; j++) {
            acc = fmaf(emb[u * 32 + j], wu[j * H1], acc);
            acc = fmaf(emb[v * 32 + j], wv[j * H1], acc);
        }
        g_cT[k * M_EDGES + e] = acc;
    } else {
        int widx = idx - 40960;                  // [0, 65536)
        int p = widx >> 13;                      // piece 0..7
        int r = widx & 8191;
        float w; u32 off;
        if ((p & 1) == 0) {
            int c = p >> 1;
            int nn = r >> 7, k = r & 127;
            w = W2[k * H2 + c * 64 + nn];
            off = (u32)(nn * 256 + k * 2) ^ (u32)((nn & 7) << 4);
        } else {
            int c = p >> 1;
            int n = r >> 6, kl = r & 63;
            w = W3[(c * 64 + kl) * H3 + n];
            off = (u32)(n * 128 + kl * 2) ^ (u32)((n & 7) << 4);
        }
        __nv_bfloat16 hi = __float2bfloat16(w);
        __nv_bfloat16 lo = __float2bfloat16(w - __bfloat162float(hi));
        *(__nv_bfloat16*)&g_Bseq[p][off] = hi;
        *(__nv_bfloat16*)&g_Bseq[p][off + 16384] = lo;
    }
}

// ================= fused MLP: persistent, 512 threads, cp.async double-buffered B =================
__device__ __forceinline__ void issue_piece(u32 dstb, int p, int tid)
{
    const char* src = (const char*)g_Bseq[p];
    #pragma unroll
    for (int i = 0; i < 4; i++) {
        int f = (tid + i * NTHREADS) * 16;
        cp16(dstb + f, src + f);
    }
    cp_commit();
}

__global__ void __launch_bounds__(NTHREADS, 1)
mlp_fused_kernel(const float* __restrict__ b2, const float* __restrict__ b3,
                 const float* __restrict__ W4)
{
    extern __shared__ unsigned char smp[];
    const u32 sb = smem_u32(smp);
    const int tid  = threadIdx.x;
    const int wid  = tid >> 5;            // 0..15
    const int lane = tid & 31;

    // l2 warp layout: 4m x 4n -> warp tile 32m x 16n (N local 64)
    const int m0_2 = (wid >> 2) * 32;
    const int n0_2 = (wid & 3) * 16;
    // l3 warp layout: 4m x 4n -> warp tile 32m x 32n (N 128)
    const int m0_3 = (wid >> 2) * 32;
    const int wn3  = wid & 3;
    const int n0_3 = wn3 * 32;

    // fragment lane constants
    const int a_krow = (lane & 7) + ((lane >> 4) << 3);     // trans-A (l2)
    const int a_cb   = ((lane >> 3) & 1) << 4;
    const int a_row  = (lane & 7) + ((lane >> 3) & 1) * 8;  // non-trans A (l3)
    const int a_kb3  = (lane >> 4) << 4;
    const int b_nrow = ((lane >> 4) << 3) + (lane & 7);     // B rows
    const int b_kb   = ((lane >> 3) & 1) << 4;
    const u32 xl     = (u32)((lane & 7) << 4);
    const u32 xk     = (u32)((a_krow & 7) << 4);

    const u32 bufs[2] = {sb + SM_B0, sb + SM_B1};

    // prefetch piece 0 into buf 0
    issue_piece(bufs[0], 0, tid);

    for (int tile = blockIdx.x; tile < NTILES; tile += GRID_MLP) {
        const int pair = tile >> 1;
        const int eb   = (tile & 1) * 128;
        const int s = pair >> 5, t = pair & 31;

        // ---- build h1 [128k][128m] hi/lo (16 warps: k = wid + 16j, m = lane*4) ----
        #pragma unroll
        for (int j = 0; j < 8; j++) {
            int k = wid + j * 16;
            float base = g_aT[k * 32 + s] + g_bT[k * 32 + t];
            u32 swz = (u32)((k & 7) << 4);
            int m = lane * 4;
            float4 c4 = *(const float4*)&g_cT[k * M_EDGES + eb + m];
            float v0 = fmaxf(base + c4.x, 0.f);
            float v1 = fmaxf(base + c4.y, 0.f);
            float v2 = fmaxf(base + c4.z, 0.f);
            float v3 = fmaxf(base + c4.w, 0.f);
            __nv_bfloat162 lp0, hp0 = split_hi(v0, v1, lp0);
            __nv_bfloat162 lp1, hp1 = split_hi(v2, v3, lp1);
            u32 off = ((u32)(k * 256 + m * 2)) ^ swz;
            *(__nv_bfloat162*)(smp + SM_A1H + off)     = hp0;
            *(__nv_bfloat162*)(smp + SM_A1H + off + 4) = hp1;
            *(__nv_bfloat162*)(smp + SM_A1L + off)     = lp0;
            *(__nv_bfloat162*)(smp + SM_A1L + off + 4) = lp1;
        }
        cp_wait0();
        __syncthreads();            // A1 ready + prefetched B2 piece 0 visible
                                    // (also guards A2 reuse vs prev tile's last L3)

        float acc3[2][4][4];
        #pragma unroll
        for (int mt = 0; mt < 2; mt++)
            #pragma unroll
            for (int nt = 0; nt < 4; nt++)
                #pragma unroll
                for (int i = 0; i < 4; i++) acc3[mt][nt][i] = 0.f;

        #pragma unroll 1
        for (int c = 0; c < 4; c++) {
            const u32 bb2 = bufs[0];       // even pieces -> buf0
            const u32 bb3 = bufs[1];       // odd pieces -> buf1

            // prefetch B3 sub c
            issue_piece(bb3, 2 * c + 1, tid);

            // ---- L2 sub-MMA: acc2 = h1 x B2[:, c*64 .. c*64+64) ----
            float acc2[2][2][4];
            #pragma unroll
            for (int mt = 0; mt < 2; mt++)
                #pragma unroll
                for (int nt = 0; nt < 2; nt++)
                    #pragma unroll
                    for (int i = 0; i < 4; i++) acc2[mt][nt][i] = 0.f;

            #pragma unroll
            for (int ks = 0; ks < 8; ks++) {
                u32 ah[2][4], al[2][4];
                #pragma unroll
                for (int mt = 0; mt < 2; mt++) {
                    u32 off = ((u32)((ks * 16 + a_krow) * 256 + (m0_2 + mt * 16) * 2 + a_cb)) ^ xk;
                    ldm_x4_t(ah[mt], sb + SM_A1H + off);
                    ldm_x4_t(al[mt], sb + SM_A1L + off);
                }
                u32 bh[4], bl[4];
                {
                    u32 off = ((u32)((n0_2 + b_nrow) * 256 + ks * 32 + b_kb)) ^ xl;
                    ldm_x4(bh, bb2 + off);
                    ldm_x4(bl, bb2 + 16384 + off);
                }
                #pragma unroll
                for (int mt = 0; mt < 2; mt++)
                    #pragma unroll
                    for (int nt = 0; nt < 2; nt++) {
                        const u32* Bh = &bh[nt * 2];
                        const u32* Bl = &bl[nt * 2];
                        mma16816(acc2[mt][nt], ah[mt], Bh);
                        mma16816(acc2[mt][nt], ah[mt], Bl);
                        mma16816(acc2[mt][nt], al[mt], Bh);
                    }
            }

            // ---- h2 epilogue -> A2 [128m][64k] ----
            #pragma unroll
            for (int nt = 0; nt < 2; nt++) {
                int nl = n0_2 + nt * 8 + (lane & 3) * 2;
                int gc = c * 64 + nl;
                float bx = __ldg(&b2[gc]), by = __ldg(&b2[gc + 1]);
                #pragma unroll
                for (int mt = 0; mt < 2; mt++) {
                    #pragma unroll
                    for (int h = 0; h < 2; h++) {
                        int row = m0_2 + mt * 16 + (lane >> 2) + h * 8;
                        float v0 = fmaxf(acc2[mt][nt][h * 2 + 0] + bx, 0.f);
                        float v1 = fmaxf(acc2[mt][nt][h * 2 + 1] + by, 0.f);
                        __nv_bfloat162 lp, hp = split_hi(v0, v1, lp);
                        u32 off = ((u32)(row * 128 + nl * 2)) ^ (u32)((row & 7) << 4);
                        *(__nv_bfloat162*)(smp + SM_A2H + off) = hp;
                        *(__nv_bfloat162*)(smp + SM_A2L + off) = lp;
                    }
                }
            }
            cp_wait0();
            __syncthreads();        // A2 visible + B3 piece ready

            // prefetch next even piece (wraps to 0 for next tile)
            issue_piece(bb2, (2 * c + 2) & 7, tid);

            // ---- L3 sub-MMA: acc3 += h2c x B3[c*64.., :] ----
            #pragma unroll
            for (int ks = 0; ks < 4; ks++) {
                u32 ah[2][4], al[2][4];
                #pragma unroll
                for (int mt = 0; mt < 2; mt++) {
                    u32 off = ((u32)((m0_3 + mt * 16 + a_row) * 128 + ks * 32 + a_kb3)) ^ xl;
                    ldm_x4(ah[mt], sb + SM_A2H + off);
                    ldm_x4(al[mt], sb + SM_A2L + off);
                }
                u32 bh[2][4], bl[2][4];
                #pragma unroll
                for (int np = 0; np < 2; np++) {
                    u32 off = ((u32)((n0_3 + np * 16 + b_nrow) * 128 + ks * 32 + b_kb)) ^ xl;
                    ldm_x4(bh[np], bb3 + off);
                    ldm_x4(bl[np], bb3 + 16384 + off);
                }
                #pragma unroll
                for (int mt = 0; mt < 2; mt++)
                    #pragma unroll
                    for (int nt = 0; nt < 4; nt++) {
                        const u32* Bh = &bh[nt >> 1][(nt & 1) * 2];
                        const u32* Bl = &bl[nt >> 1][(nt & 1) * 2];
                        mma16816(acc3[mt][nt], ah[mt], Bh);
                        mma16816(acc3[mt][nt], ah[mt], Bl);
                        mma16816(acc3[mt][nt], al[mt], Bh);
                    }
            }
            if (c < 3) {            // last chunk: covered by next tile's post-h1 barrier
                cp_wait0();
                __syncthreads();    // A2 free for next epilogue + next B2 ready
            }
        }

        // ---- layer 4: partial pred per warp-column -> g_preds4 (no barriers) ----
        #pragma unroll
        for (int mt = 0; mt < 2; mt++) {
            #pragma unroll
            for (int h = 0; h < 2; h++) {
                float part = 0.f;
                #pragma unroll
                for (int nt = 0; nt < 4; nt++) {
                    int cc = n0_3 + nt * 8 + (lane & 3) * 2;
                    float h0 = fmaxf(acc3[mt][nt][h * 2 + 0] + __ldg(&b3[cc]), 0.f);
                    float h1 = fmaxf(acc3[mt][nt][h * 2 + 1] + __ldg(&b3[cc + 1]), 0.f);
                    part = fmaf(h0, __ldg(&W4[cc]), part);
                    part = fmaf(h1, __ldg(&W4[cc + 1]), part);
                }
                part += __shfl_xor_sync(0xffffffffu, part, 1);
                part += __shfl_xor_sync(0xffffffffu, part, 2);
                if ((lane & 3) == 0) {
                    int row = m0_3 + mt * 16 + (lane >> 2) + h * 8;
                    g_preds4[wn3][pair * M_EDGES + eb + row] = part;
                }
            }
        }
    }
    cp_wait0();
}

// ---------------- kernel 3: fused partial-sum + scatter + power iteration + final reduce ----------------
// grid 128 x 256: one warp per (s,t) pair; last CTA to finish also does the global reduction.
__global__ void power_kernel(const int* __restrict__ edges, const float* __restrict__ b4,
                             float* __restrict__ out)
{
    __shared__ float As[8][1024];
    __shared__ float red2[8][33];
    __shared__ int   isLast;
    const int wid  = threadIdx.x >> 5;
    const int lane = threadIdx.x & 31;
    const int p    = blockIdx.x * 8 + wid;
    float* A = As[wid];
    const float b4v = __ldg(&b4[0]);

    #pragma unroll
    for (int i = lane; i < 1024; i += 32) A[i] = 0.f;
    __syncwarp();

    #pragma unroll
    for (int j = 0; j < 8; j++) {
        int e = j * 32 + lane;
        int base = p * M_EDGES + e;
        float pred = ((g_preds4[0][base] + g_preds4[1][base])
                    + (g_preds4[2][base] + g_preds4[3][base])) + b4v;
        int u = edges[2 * e], v = edges[2 * e + 1];
        atomicAdd(&A[u * 32 + v], pred);
    }
    __syncwarp();

    const int s = p >> 5, t = p & 31;
    if (lane == 0) A[s * 32 + s] += 1.f;
    __syncwarp();

    float col[32];                       // A[:, lane]
    #pragma unroll
    for (int u = 0; u < 32; u++) col[u] = A[u * 32 + lane];

    // Power iteration with sparse normalization: normalization is a pure scalar on
    // the iterate (direction-preserving); normalize every 4th step + final step to
    // keep magnitudes in range. Final step uses the reference formula (norm + eps).
    float x = 1.0f / 32.0f;
    #pragma unroll 1
    for (int it = 0; it < 50; it++) {
        float a0 = 0.f, a1 = 0.f, a2 = 0.f, a3 = 0.f;
        #pragma unroll
        for (int u = 0; u < 32; u += 4) {
            a0 = fmaf(__shfl_sync(0xffffffffu, x, u),     col[u],     a0);
            a1 = fmaf(__shfl_sync(0xffffffffu, x, u + 1), col[u + 1], a1);
            a2 = fmaf(__shfl_sync(0xffffffffu, x, u + 2), col[u + 2], a2);
            a3 = fmaf(__shfl_sync(0xffffffffu, x, u + 3), col[u + 3], a3);
        }
        float acc = (a0 + a1) + (a2 + a3);
        if (((it & 3) == 3) || it == 49) {
            float ss = acc * acc;
            #pragma unroll
            for (int o = 16; o > 0; o >>= 1)
                ss += __shfl_xor_sync(0xffffffffu, ss, o);
            x = acc / (sqrtf(ss) + EPSF);
        } else {
            x = acc;
        }
    }
    float xs = __shfl_sync(0xffffffffu, x, s);
    float d = (s != t) ? x / (xs + EPSF) : 0.f;
    g_delta[p * 32 + lane] = d;

    // ---- last-block-done global reduction (deterministic order) ----
    __syncthreads();
    if (threadIdx.x == 0) {
        __threadfence();
        int done = atomicAdd(&g_ctr, 1);
        isLast = (done == gridDim.x - 1) ? 1 : 0;
    }
    __syncthreads();
    if (isLast) {
        __threadfence();
        int v = threadIdx.x & 31, g = threadIdx.x >> 5;   // 8 groups x 32
        float acc = 0.f;
        #pragma unroll 8
        for (int pp = g; pp < NPAIR; pp += 8)
            acc += g_delta[pp * 32 + v];
        red2[g][v] = acc;
        __syncthreads();
        if (g == 0) {
            float r = ((red2[0][v] + red2[1][v]) + (red2[2][v] + red2[3][v]))
                    + ((red2[4][v] + red2[5][v]) + (red2[6][v] + red2[7][v]));
            float tot = r;
            #pragma unroll
            for (int o = 16; o > 0; o >>= 1)
                tot += __shfl_xor_sync(0xffffffffu, tot, o);
            out[v] = r / tot;
        }
    }
}

// ---------------- launch ----------------
extern "C" void kernel_launch(void* const* d_in, const int* in_sizes, int n_in,
                              void* d_out, int out_size)
{
    (void)in_sizes; (void)n_in; (void)out_size;
    const float* emb   = (const float*)d_in[1];
    const int*   edges = (const int*)  d_in[2];
    const float* W1 = (const float*)d_in[3];
    const float* b1 = (const float*)d_in[4];
    const float* W2 = (const float*)d_in[5];
    const float* b2 = (const float*)d_in[6];
    const float* W3 = (const float*)d_in[7];
    const float* b3 = (const float*)d_in[8];
    const float* W4 = (const float*)d_in[9];
    const float* b4 = (const float*)d_in[10];
    float* out = (float*)d_out;

    static int attr_set = 0;
    if (!attr_set) {
        cudaFuncSetAttribute(mlp_fused_kernel, cudaFuncAttributeMaxDynamicSharedMemorySize, SM_TOTAL);
        attr_set = 1;
    }

    prep_all_kernel <<<416, 256>>>(emb, edges, W1, b1, W2, W3);
    mlp_fused_kernel<<<GRID_MLP, NTHREADS, SM_TOTAL>>>(b2, b3, W4);
    power_kernel    <<<128, 256>>>(edges, b4, out);
}

// round 14
// speedup vs baseline: 2.1035x; 1.0307x over previous
#include <cuda_runtime.h>
#include <cuda_bf16.h>
#include <cstdint>

#define N_NODES 32
#define M_EDGES 256
#define H1 128
#define H2 256
#define H3 128
#define NPAIR 1024
#define EPSF 1e-9f
#define NTILES 2048          // pair * 2 halves of 128 edge-rows
#define GRID_MLP 152
#define NTHREADS 512

typedef uint32_t u32;

// ---------------- scratch (no allocations allowed) ----------------
__device__ float g_aT[N_NODES * H1];             // s-major: [s][k]
__device__ float g_bT[N_NODES * H1];             // t-major: [t][k]
__device__ float g_cT[H1 * M_EDGES];             // k-major: [k][e]
__device__ float g_preds4[4][NPAIR * M_EDGES];   // per-warp-column partial preds
__device__ float g_delta[NPAIR * N_NODES];
__device__ int   g_ctr;                          // last-block-done counter
// 8 cyclic pre-swizzled weight pieces, 32KB each: [hi 16KB | lo 16KB]
__device__ __align__(16) unsigned char g_Bseq[8][32768];

// ---------------- smem layout (bytes) ----------------
#define SM_A1H 0                       // h1 hi, [128k][128m], 256B rows, 32KB
#define SM_A1L 32768                   // h1 lo
#define SM_A2H 65536                   // h2 sub hi, [128m][64k], 128B rows, 16KB
#define SM_A2L 81920                   // h2 sub lo
#define SM_B0  98304                   // B ring buf 0 (32KB)
#define SM_B1  131072                  // B ring buf 1 (32KB)
#define SM_TOTAL 163840

// ---------------- PTX helpers ----------------
__device__ __forceinline__ u32 smem_u32(const void* p) {
    u32 a; asm("{ .reg .u64 t; cvta.to.shared.u64 t, %1; cvt.u32.u64 %0, t; }" : "=r"(a) : "l"(p));
    return a;
}
__device__ __forceinline__ void ldm_x4(u32 r[4], u32 addr) {
    asm volatile("ldmatrix.sync.aligned.m8n8.x4.shared.b16 {%0,%1,%2,%3}, [%4];"
                 : "=r"(r[0]), "=r"(r[1]), "=r"(r[2]), "=r"(r[3]) : "r"(addr));
}
__device__ __forceinline__ void ldm_x4_t(u32 r[4], u32 addr) {
    asm volatile("ldmatrix.sync.aligned.m8n8.x4.trans.shared.b16 {%0,%1,%2,%3}, [%4];"
                 : "=r"(r[0]), "=r"(r[1]), "=r"(r[2]), "=r"(r[3]) : "r"(addr));
}
__device__ __forceinline__ void mma16816(float c[4], const u32 a[4], const u32 b[2]) {
    asm volatile("mma.sync.aligned.m16n8k16.row.col.f32.bf16.bf16.f32 "
                 "{%0,%1,%2,%3}, {%4,%5,%6,%7}, {%8,%9}, {%0,%1,%2,%3};"
                 : "+f"(c[0]), "+f"(c[1]), "+f"(c[2]), "+f"(c[3])
                 : "r"(a[0]), "r"(a[1]), "r"(a[2]), "r"(a[3]), "r"(b[0]), "r"(b[1]));
}
__device__ __forceinline__ void cp16(u32 dst, const void* src) {
    asm volatile("cp.async.cg.shared.global [%0], [%1], 16;" :: "r"(dst), "l"(src) : "memory");
}
__device__ __forceinline__ void cp_commit() {
    asm volatile("cp.async.commit_group;" ::: "memory");
}
__device__ __forceinline__ void cp_wait0() {
    asm volatile("cp.async.wait_group 0;" ::: "memory");
}
__device__ __forceinline__ __nv_bfloat162 split_hi(float v0, float v1, __nv_bfloat162& lo) {
    __nv_bfloat162 hi;
    hi.x = __float2bfloat16(v0); hi.y = __float2bfloat16(v1);
    lo.x = __float2bfloat16(v0 - __bfloat162float(hi.x));
    lo.y = __float2bfloat16(v1 - __bfloat162float(hi.y));
    return hi;
}

// ---------------- kernel 1: factored layer-1 partials + weight split/swizzle ----------------
// Lane mappings chosen so EVERY load is coalesced (lanes sweep the contiguous
// gmem dim) or warp-broadcast; scattered accesses are stores only.
// 106496 threads = 416 x 256: [0,8192) aT/bT, [8192,40960) cT, [40960,106496) weights
__global__ void prep_all_kernel(const float* __restrict__ emb,
                                const int*   __restrict__ edges,
                                const float* __restrict__ W1,
                                const float* __restrict__ b1,
                                const float* __restrict__ W2,
                                const float* __restrict__ W3)
{
    int idx = blockIdx.x * blockDim.x + threadIdx.x;
    if (idx == 0) g_ctr = 0;                     // reset last-block counter (deterministic per replay)
    if (idx < 2 * H1 * N_NODES) {
        // aT/bT: lanes vary k (W1-contiguous). emb broadcast per warp.
        int sec = idx >> 12;
        int r = idx & 4095;
        int s = r >> 7, k = r & 127;
        const float* w = W1 + (sec ? (32 * H1) : 0) + k;
        float acc = 0.f;
        #pragma unroll
        for (int j = 0; j < 32; j++)
            acc = fmaf(emb[s * 32 + j], w[j * H1], acc);
        (sec ? g_bT : g_aT)[s * H1 + k] = acc;   // coalesced store
    } else if (idx < 40960) {
        // cT: lanes vary k. edges/emb broadcast per warp; W1 coalesced.
        int r = idx - 2 * H1 * N_NODES;          // [0, 32768)
        int e = r >> 7, k = r & 127;
        int u = edges[2 * e], v = edges[2 * e + 1];
        const float* wu = W1 + 64 * H1 + k;
        const float* wv = W1 + 96 * H1 + k;
        float acc = b1[k];
        #pragma unroll
        for (int j = 0; j < 32; j++) {
            acc = fmaf(emb[u * 32 + j], wu[j * H1], acc);
            acc = fmaf(emb[v * 32 + j], wv[j * H1], acc);
        }
        g_cT[k * M_EDGES + e] = acc;             // scattered store (issue-cost only)
    } else {
        // weights: lanes vary n (the W2/W3-contiguous dim); store scattered+swizzled.
        int widx = idx - 40960;                  // [0, 65536)
        int p = widx >> 13;                      // piece 0..7
        int r = widx & 8191;
        float w; u32 off;
        if ((p & 1) == 0) {
            int c = p >> 1;
            int nn = r & 63, k = r >> 6;         // lanes sweep nn -> coalesced load
            w = W2[k * H2 + c * 64 + nn];
            off = (u32)(nn * 256 + k * 2) ^ (u32)((nn & 7) << 4);
        } else {
            int c = p >> 1;
            int n = r & 127, kl = r >> 7;        // lanes sweep n -> coalesced load
            w = W3[(c * 64 + kl) * H3 + n];
            off = (u32)(n * 128 + kl * 2) ^ (u32)((n & 7) << 4);
        }
        __nv_bfloat16 hi = __float2bfloat16(w);
        __nv_bfloat16 lo = __float2bfloat16(w - __bfloat162float(hi));
        *(__nv_bfloat16*)&g_Bseq[p][off] = hi;
        *(__nv_bfloat16*)&g_Bseq[p][off + 16384] = lo;
    }
}

// ================= fused MLP: persistent, 512 threads, cp.async double-buffered B =================
__device__ __forceinline__ void issue_piece(u32 dstb, int p, int tid)
{
    const char* src = (const char*)g_Bseq[p];
    #pragma unroll
    for (int i = 0; i < 4; i++) {
        int f = (tid + i * NTHREADS) * 16;
        cp16(dstb + f, src + f);
    }
    cp_commit();
}

__global__ void __launch_bounds__(NTHREADS, 1)
mlp_fused_kernel(const float* __restrict__ b2, const float* __restrict__ b3,
                 const float* __restrict__ W4)
{
    extern __shared__ unsigned char smp[];
    const u32 sb = smem_u32(smp);
    const int tid  = threadIdx.x;
    const int wid  = tid >> 5;            // 0..15
    const int lane = tid & 31;

    // l2 warp layout: 4m x 4n -> warp tile 32m x 16n (N local 64)
    const int m0_2 = (wid >> 2) * 32;
    const int n0_2 = (wid & 3) * 16;
    // l3 warp layout: 4m x 4n -> warp tile 32m x 32n (N 128)
    const int m0_3 = (wid >> 2) * 32;
    const int wn3  = wid & 3;
    const int n0_3 = wn3 * 32;

    // fragment lane constants
    const int a_krow = (lane & 7) + ((lane >> 4) << 3);     // trans-A (l2)
    const int a_cb   = ((lane >> 3) & 1) << 4;
    const int a_row  = (lane & 7) + ((lane >> 3) & 1) * 8;  // non-trans A (l3)
    const int a_kb3  = (lane >> 4) << 4;
    const int b_nrow = ((lane >> 4) << 3) + (lane & 7);     // B rows
    const int b_kb   = ((lane >> 3) & 1) << 4;
    const u32 xl     = (u32)((lane & 7) << 4);
    const u32 xk     = (u32)((a_krow & 7) << 4);

    const u32 bufs[2] = {sb + SM_B0, sb + SM_B1};

    // prefetch piece 0 into buf 0
    issue_piece(bufs[0], 0, tid);

    for (int tile = blockIdx.x; tile < NTILES; tile += GRID_MLP) {
        const int pair = tile >> 1;
        const int eb   = (tile & 1) * 128;
        const int s = pair >> 5, t = pair & 31;

        // ---- build h1 [128k][128m] hi/lo (16 warps: k = wid + 16j, m = lane*4) ----
        #pragma unroll
        for (int j = 0; j < 8; j++) {
            int k = wid + j * 16;
            float base = g_aT[s * H1 + k] + g_bT[t * H1 + k];
            u32 swz = (u32)((k & 7) << 4);
            int m = lane * 4;
            float4 c4 = *(const float4*)&g_cT[k * M_EDGES + eb + m];
            float v0 = fmaxf(base + c4.x, 0.f);
            float v1 = fmaxf(base + c4.y, 0.f);
            float v2 = fmaxf(base + c4.z, 0.f);
            float v3 = fmaxf(base + c4.w, 0.f);
            __nv_bfloat162 lp0, hp0 = split_hi(v0, v1, lp0);
            __nv_bfloat162 lp1, hp1 = split_hi(v2, v3, lp1);
            u32 off = ((u32)(k * 256 + m * 2)) ^ swz;
            *(__nv_bfloat162*)(smp + SM_A1H + off)     = hp0;
            *(__nv_bfloat162*)(smp + SM_A1H + off + 4) = hp1;
            *(__nv_bfloat162*)(smp + SM_A1L + off)     = lp0;
            *(__nv_bfloat162*)(smp + SM_A1L + off + 4) = lp1;
        }
        cp_wait0();
        __syncthreads();            // A1 ready + prefetched B2 piece 0 visible
                                    // (also guards A2 reuse vs prev tile's last L3)

        float acc3[2][4][4];
        #pragma unroll
        for (int mt = 0; mt < 2; mt++)
            #pragma unroll
            for (int nt = 0; nt < 4; nt++)
                #pragma unroll
                for (int i = 0; i < 4; i++) acc3[mt][nt][i] = 0.f;

        #pragma unroll 1
        for (int c = 0; c < 4; c++) {
            const u32 bb2 = bufs[0];       // even pieces -> buf0
            const u32 bb3 = bufs[1];       // odd pieces -> buf1

            // prefetch B3 sub c
            issue_piece(bb3, 2 * c + 1, tid);

            // ---- L2 sub-MMA: acc2 = h1 x B2[:, c*64 .. c*64+64) ----
            float acc2[2][2][4];
            #pragma unroll
            for (int mt = 0; mt < 2; mt++)
                #pragma unroll
                for (int nt = 0; nt < 2; nt++)
                    #pragma unroll
                    for (int i = 0; i < 4; i++) acc2[mt][nt][i] = 0.f;

            #pragma unroll
            for (int ks = 0; ks < 8; ks++) {
                u32 ah[2][4], al[2][4];
                #pragma unroll
                for (int mt = 0; mt < 2; mt++) {
                    u32 off = ((u32)((ks * 16 + a_krow) * 256 + (m0_2 + mt * 16) * 2 + a_cb)) ^ xk;
                    ldm_x4_t(ah[mt], sb + SM_A1H + off);
                    ldm_x4_t(al[mt], sb + SM_A1L + off);
                }
                u32 bh[4], bl[4];
                {
                    u32 off = ((u32)((n0_2 + b_nrow) * 256 + ks * 32 + b_kb)) ^ xl;
                    ldm_x4(bh, bb2 + off);
                    ldm_x4(bl, bb2 + 16384 + off);
                }
                #pragma unroll
                for (int mt = 0; mt < 2; mt++)
                    #pragma unroll
                    for (int nt = 0; nt < 2; nt++) {
                        const u32* Bh = &bh[nt * 2];
                        const u32* Bl = &bl[nt * 2];
                        mma16816(acc2[mt][nt], ah[mt], Bh);
                        mma16816(acc2[mt][nt], ah[mt], Bl);
                        mma16816(acc2[mt][nt], al[mt], Bh);
                    }
            }

            // ---- h2 epilogue -> A2 [128m][64k] ----
            #pragma unroll
            for (int nt = 0; nt < 2; nt++) {
                int nl = n0_2 + nt * 8 + (lane & 3) * 2;
                int gc = c * 64 + nl;
                float bx = __ldg(&b2[gc]), by = __ldg(&b2[gc + 1]);
                #pragma unroll
                for (int mt = 0; mt < 2; mt++) {
                    #pragma unroll
                    for (int h = 0; h < 2; h++) {
                        int row = m0_2 + mt * 16 + (lane >> 2) + h * 8;
                        float v0 = fmaxf(acc2[mt][nt][h * 2 + 0] + bx, 0.f);
                        float v1 = fmaxf(acc2[mt][nt][h * 2 + 1] + by, 0.f);
                        __nv_bfloat162 lp, hp = split_hi(v0, v1, lp);
                        u32 off = ((u32)(row * 128 + nl * 2)) ^ (u32)((row & 7) << 4);
                        *(__nv_bfloat162*)(smp + SM_A2H + off) = hp;
                        *(__nv_bfloat162*)(smp + SM_A2L + off) = lp;
                    }
                }
            }
            cp_wait0();
            __syncthreads();        // A2 visible + B3 piece ready

            // prefetch next even piece (wraps to 0 for next tile)
            issue_piece(bb2, (2 * c + 2) & 7, tid);

            // ---- L3 sub-MMA: acc3 += h2c x B3[c*64.., :] ----
            #pragma unroll
            for (int ks = 0; ks < 4; ks++) {
                u32 ah[2][4], al[2][4];
                #pragma unroll
                for (int mt = 0; mt < 2; mt++) {
                    u32 off = ((u32)((m0_3 + mt * 16 + a_row) * 128 + ks * 32 + a_kb3)) ^ xl;
                    ldm_x4(ah[mt], sb + SM_A2H + off);
                    ldm_x4(al[mt], sb + SM_A2L + off);
                }
                u32 bh[2][4], bl[2][4];
                #pragma unroll
                for (int np = 0; np < 2; np++) {
                    u32 off = ((u32)((n0_3 + np * 16 + b_nrow) * 128 + ks * 32 + b_kb)) ^ xl;
                    ldm_x4(bh[np], bb3 + off);
                    ldm_x4(bl[np], bb3 + 16384 + off);
                }
                #pragma unroll
                for (int mt = 0; mt < 2; mt++)
                    #pragma unroll
                    for (int nt = 0; nt < 4; nt++) {
                        const u32* Bh = &bh[nt >> 1][(nt & 1) * 2];
                        const u32* Bl = &bl[nt >> 1][(nt & 1) * 2];
                        mma16816(acc3[mt][nt], ah[mt], Bh);
                        mma16816(acc3[mt][nt], ah[mt], Bl);
                        mma16816(acc3[mt][nt], al[mt], Bh);
                    }
            }
            if (c < 3) {            // last chunk: covered by next tile's post-h1 barrier
                cp_wait0();
                __syncthreads();    // A2 free for next epilogue + next B2 ready
            }
        }

        // ---- layer 4: partial pred per warp-column -> g_preds4 (no barriers) ----
        #pragma unroll
        for (int mt = 0; mt < 2; mt++) {
            #pragma unroll
            for (int h = 0; h < 2; h++) {
                float part = 0.f;
                #pragma unroll
                for (int nt = 0; nt < 4; nt++) {
                    int cc = n0_3 + nt * 8 + (lane & 3) * 2;
                    float h0 = fmaxf(acc3[mt][nt][h * 2 + 0] + __ldg(&b3[cc]), 0.f);
                    float h1 = fmaxf(acc3[mt][nt][h * 2 + 1] + __ldg(&b3[cc + 1]), 0.f);
                    part = fmaf(h0, __ldg(&W4[cc]), part);
                    part = fmaf(h1, __ldg(&W4[cc + 1]), part);
                }
                part += __shfl_xor_sync(0xffffffffu, part, 1);
                part += __shfl_xor_sync(0xffffffffu, part, 2);
                if ((lane & 3) == 0) {
                    int row = m0_3 + mt * 16 + (lane >> 2) + h * 8;
                    g_preds4[wn3][pair * M_EDGES + eb + row] = part;
                }
            }
        }
    }
    cp_wait0();
}

// ---------------- kernel 3: fused partial-sum + scatter + power iteration + final reduce ----------------
// grid 128 x 256: one warp per (s,t) pair; last CTA to finish also does the global reduction.
__global__ void power_kernel(const int* __restrict__ edges, const float* __restrict__ b4,
                             float* __restrict__ out)
{
    __shared__ float As[8][1024];
    __shared__ float red2[8][33];
    __shared__ int   isLast;
    const int wid  = threadIdx.x >> 5;
    const int lane = threadIdx.x & 31;
    const int p    = blockIdx.x * 8 + wid;
    float* A = As[wid];
    const float b4v = __ldg(&b4[0]);

    #pragma unroll
    for (int i = lane; i < 1024; i += 32) A[i] = 0.f;
    __syncwarp();

    #pragma unroll
    for (int j = 0; j < 8; j++) {
        int e = j * 32 + lane;
        int base = p * M_EDGES + e;
        float pred = ((g_preds4[0][base] + g_preds4[1][base])
                    + (g_preds4[2][base] + g_preds4[3][base])) + b4v;
        int u = edges[2 * e], v = edges[2 * e + 1];
        atomicAdd(&A[u * 32 + v], pred);
    }
    __syncwarp();

    const int s = p >> 5, t = p & 31;
    if (lane == 0) A[s * 32 + s] += 1.f;
    __syncwarp();

    float col[32];                       // A[:, lane]
    #pragma unroll
    for (int u = 0; u < 32; u++) col[u] = A[u * 32 + lane];

    // Power iteration with sparse normalization (direction-preserving scalar).
    float x = 1.0f / 32.0f;
    #pragma unroll 1
    for (int it = 0; it < 50; it++) {
        float a0 = 0.f, a1 = 0.f, a2 = 0.f, a3 = 0.f;
        #pragma unroll
        for (int u = 0; u < 32; u += 4) {
            a0 = fmaf(__shfl_sync(0xffffffffu, x, u),     col[u],     a0);
            a1 = fmaf(__shfl_sync(0xffffffffu, x, u + 1), col[u + 1], a1);
            a2 = fmaf(__shfl_sync(0xffffffffu, x, u + 2), col[u + 2], a2);
            a3 = fmaf(__shfl_sync(0xffffffffu, x, u + 3), col[u + 3], a3);
        }
        float acc = (a0 + a1) + (a2 + a3);
        if (((it & 3) == 3) || it == 49) {
            float ss = acc * acc;
            #pragma unroll
            for (int o = 16; o > 0; o >>= 1)
                ss += __shfl_xor_sync(0xffffffffu, ss, o);
            x = acc / (sqrtf(ss) + EPSF);
        } else {
            x = acc;
        }
    }
    float xs = __shfl_sync(0xffffffffu, x, s);
    float d = (s != t) ? x / (xs + EPSF) : 0.f;
    g_delta[p * 32 + lane] = d;

    // ---- last-block-done global reduction (deterministic order) ----
    __syncthreads();
    if (threadIdx.x == 0) {
        __threadfence();
        int done = atomicAdd(&g_ctr, 1);
        isLast = (done == gridDim.x - 1) ? 1 : 0;
    }
    __syncthreads();
    if (isLast) {
        __threadfence();
        int v = threadIdx.x & 31, g = threadIdx.x >> 5;   // 8 groups x 32
        float acc = 0.f;
        #pragma unroll 8
        for (int pp = g; pp < NPAIR; pp += 8)
            acc += g_delta[pp * 32 + v];
        red2[g][v] = acc;
        __syncthreads();
        if (g == 0) {
            float r = ((red2[0][v] + red2[1][v]) + (red2[2][v] + red2[3][v]))
                    + ((red2[4][v] + red2[5][v]) + (red2[6][v] + red2[7][v]));
            float tot = r;
            #pragma unroll
            for (int o = 16; o > 0; o >>= 1)
                tot += __shfl_xor_sync(0xffffffffu, tot, o);
            out[v] = r / tot;
        }
    }
}

// ---------------- launch ----------------
extern "C" void kernel_launch(void* const* d_in, const int* in_sizes, int n_in,
                              void* d_out, int out_size)
{
    (void)in_sizes; (void)n_in; (void)out_size;
    const float* emb   = (const float*)d_in[1];
    const int*   edges = (const int*)  d_in[2];
    const float* W1 = (const float*)d_in[3];
    const float* b1 = (const float*)d_in[4];
    const float* W2 = (const float*)d_in[5];
    const float* b2 = (const float*)d_in[6];
    const float* W3 = (const float*)d_in[7];
    const float* b3 = (const float*)d_in[8];
    const float* W4 = (const float*)d_in[9];
    const float* b4 = (const float*)d_in[10];
    float* out = (float*)d_out;

    static int attr_set = 0;
    if (!attr_set) {
        cudaFuncSetAttribute(mlp_fused_kernel, cudaFuncAttributeMaxDynamicSharedMemorySize, SM_TOTAL);
        attr_set = 1;
    }

    prep_all_kernel <<<416, 256>>>(emb, edges, W1, b1, W2, W3);
    mlp_fused_kernel<<<GRID_MLP, NTHREADS, SM_TOTAL>>>(b2, b3, W4);
    power_kernel    <<<128, 256>>>(edges, b4, out);
}

// round 15
// speedup vs baseline: 2.1631x; 1.0283x over previous
#include <cuda_runtime.h>
#include <cuda_bf16.h>
#include <cstdint>

#define N_NODES 32
#define M_EDGES 256
#define H1 128
#define H2 256
#define H3 128
#define NPAIR 1024
#define EPSF 1e-9f
#define GRID_MLP 152
#define NTHREADS 512
#define FULL_ROUNDS 13          // 152*13 = 1976 full tiles
#define NHALF 144               // remaining 72 tiles -> 144 half-tiles (64 rows)

typedef uint32_t u32;

// ---------------- scratch (no allocations allowed) ----------------
__device__ float g_aT[N_NODES * H1];             // s-major: [s][k]
__device__ float g_bT[N_NODES * H1];             // t-major: [t][k]
__device__ float g_cT[H1 * M_EDGES];             // k-major: [k][e]
__device__ float g_preds4[4][NPAIR * M_EDGES];   // per-warp-column partial preds
__device__ float g_delta[NPAIR * N_NODES];
__device__ int   g_ctr;                          // last-block-done counter
// 8 cyclic pre-swizzled weight pieces, 32KB each: [hi 16KB | lo 16KB]
__device__ __align__(16) unsigned char g_Bseq[8][32768];

// ---------------- smem layout (bytes) ----------------
#define SM_A1H 0                       // h1 hi, [128k][128m], 256B rows, 32KB
#define SM_A1L 32768                   // h1 lo
#define SM_A2H 65536                   // h2 sub hi, [128m][64k], 128B rows, 16KB
#define SM_A2L 81920                   // h2 sub lo
#define SM_B0  98304                   // B ring buf 0 (32KB)
#define SM_B1  131072                  // B ring buf 1 (32KB)
#define SM_TOTAL 163840

// ---------------- PTX helpers ----------------
__device__ __forceinline__ u32 smem_u32(const void* p) {
    u32 a; asm("{ .reg .u64 t; cvta.to.shared.u64 t, %1; cvt.u32.u64 %0, t; }" : "=r"(a) : "l"(p));
    return a;
}
__device__ __forceinline__ void ldm_x4(u32 r[4], u32 addr) {
    asm volatile("ldmatrix.sync.aligned.m8n8.x4.shared.b16 {%0,%1,%2,%3}, [%4];"
                 : "=r"(r[0]), "=r"(r[1]), "=r"(r[2]), "=r"(r[3]) : "r"(addr));
}
__device__ __forceinline__ void ldm_x4_t(u32 r[4], u32 addr) {
    asm volatile("ldmatrix.sync.aligned.m8n8.x4.trans.shared.b16 {%0,%1,%2,%3}, [%4];"
                 : "=r"(r[0]), "=r"(r[1]), "=r"(r[2]), "=r"(r[3]) : "r"(addr));
}
__device__ __forceinline__ void mma16816(float c[4], const u32 a[4], const u32 b[2]) {
    asm volatile("mma.sync.aligned.m16n8k16.row.col.f32.bf16.bf16.f32 "
                 "{%0,%1,%2,%3}, {%4,%5,%6,%7}, {%8,%9}, {%0,%1,%2,%3};"
                 : "+f"(c[0]), "+f"(c[1]), "+f"(c[2]), "+f"(c[3])
                 : "r"(a[0]), "r"(a[1]), "r"(a[2]), "r"(a[3]), "r"(b[0]), "r"(b[1]));
}
__device__ __forceinline__ void cp16(u32 dst, const void* src) {
    asm volatile("cp.async.cg.shared.global [%0], [%1], 16;" :: "r"(dst), "l"(src) : "memory");
}
__device__ __forceinline__ void cp_commit() {
    asm volatile("cp.async.commit_group;" ::: "memory");
}
__device__ __forceinline__ void cp_wait0() {
    asm volatile("cp.async.wait_group 0;" ::: "memory");
}
__device__ __forceinline__ __nv_bfloat162 split_hi(float v0, float v1, __nv_bfloat162& lo) {
    __nv_bfloat162 hi;
    hi.x = __float2bfloat16(v0); hi.y = __float2bfloat16(v1);
    lo.x = __float2bfloat16(v0 - __bfloat162float(hi.x));
    lo.y = __float2bfloat16(v1 - __bfloat162float(hi.y));
    return hi;
}

// ---------------- kernel 1: factored layer-1 partials + weight split/swizzle ----------------
// All loads coalesced or warp-broadcast; scattered accesses are stores only.
__global__ void prep_all_kernel(const float* __restrict__ emb,
                                const int*   __restrict__ edges,
                                const float* __restrict__ W1,
                                const float* __restrict__ b1,
                                const float* __restrict__ W2,
                                const float* __restrict__ W3)
{
    int idx = blockIdx.x * blockDim.x + threadIdx.x;
    if (idx == 0) g_ctr = 0;                     // reset last-block counter (deterministic per replay)
    if (idx < 2 * H1 * N_NODES) {
        // aT/bT: lanes vary k (W1-contiguous). emb broadcast per warp. 2 fma chains.
        int sec = idx >> 12;
        int r = idx & 4095;
        int s = r >> 7, k = r & 127;
        const float* w = W1 + (sec ? (32 * H1) : 0) + k;
        float acc0 = 0.f, acc1 = 0.f;
        #pragma unroll
        for (int j = 0; j < 32; j += 2) {
            acc0 = fmaf(emb[s * 32 + j],     w[j * H1],       acc0);
            acc1 = fmaf(emb[s * 32 + j + 1], w[(j + 1) * H1], acc1);
        }
        (sec ? g_bT : g_aT)[s * H1 + k] = acc0 + acc1;
    } else if (idx < 40960) {
        // cT: lanes vary k. edges/emb broadcast; W1 coalesced. 2 chains.
        int r = idx - 2 * H1 * N_NODES;          // [0, 32768)
        int e = r >> 7, k = r & 127;
        int u = edges[2 * e], v = edges[2 * e + 1];
        const float* wu = W1 + 64 * H1 + k;
        const float* wv = W1 + 96 * H1 + k;
        float acc0 = b1[k], acc1 = 0.f;
        #pragma unroll
        for (int j = 0; j < 32; j++) {
            acc0 = fmaf(emb[u * 32 + j], wu[j * H1], acc0);
            acc1 = fmaf(emb[v * 32 + j], wv[j * H1], acc1);
        }
        g_cT[k * M_EDGES + e] = acc0 + acc1;
    } else {
        // weights: lanes vary n (contiguous dim); scattered swizzled stores.
        int widx = idx - 40960;                  // [0, 65536)
        int p = widx >> 13;                      // piece 0..7
        int r = widx & 8191;
        float w; u32 off;
        if ((p & 1) == 0) {
            int c = p >> 1;
            int nn = r & 63, k = r >> 6;
            w = W2[k * H2 + c * 64 + nn];
            off = (u32)(nn * 256 + k * 2) ^ (u32)((nn & 7) << 4);
        } else {
            int c = p >> 1;
            int n = r & 127, kl = r >> 7;
            w = W3[(c * 64 + kl) * H3 + n];
            off = (u32)(n * 128 + kl * 2) ^ (u32)((n & 7) << 4);
        }
        __nv_bfloat16 hi = __float2bfloat16(w);
        __nv_bfloat16 lo = __float2bfloat16(w - __bfloat162float(hi));
        *(__nv_bfloat16*)&g_Bseq[p][off] = hi;
        *(__nv_bfloat16*)&g_Bseq[p][off + 16384] = lo;
    }
}

// ================= fused MLP: persistent, 512 threads, cp.async double-buffered B =================
__device__ __forceinline__ void issue_piece(u32 dstb, int p, int tid)
{
    const char* src = (const char*)g_Bseq[p];
    #pragma unroll
    for (int i = 0; i < 4; i++) {
        int f = (tid + i * NTHREADS) * 16;
        cp16(dstb + f, src + f);
    }
    cp_commit();
}

__global__ void __launch_bounds__(NTHREADS, 1)
mlp_fused_kernel(const float* __restrict__ b2, const float* __restrict__ b3,
                 const float* __restrict__ W4)
{
    extern __shared__ unsigned char smp[];
    const u32 sb = smem_u32(smp);
    const int tid  = threadIdx.x;
    const int wid  = tid >> 5;            // 0..15
    const int lane = tid & 31;
    const int bid  = blockIdx.x;

    // l2 warp layout: 4m x 4n -> warp tile 32m x 16n (N local 64)
    const int m0_2 = (wid >> 2) * 32;
    const int n0_2 = (wid & 3) * 16;
    // l3 warp layout: 4m x 4n -> warp tile 32m x 32n (N 128)
    const int m0_3 = (wid >> 2) * 32;
    const int wn3  = wid & 3;
    const int n0_3 = wn3 * 32;
    const int mgrp = wid >> 2;

    // fragment lane constants
    const int a_krow = (lane & 7) + ((lane >> 4) << 3);     // trans-A (l2)
    const int a_cb   = ((lane >> 3) & 1) << 4;
    const int a_row  = (lane & 7) + ((lane >> 3) & 1) * 8;  // non-trans A (l3)
    const int a_kb3  = (lane >> 4) << 4;
    const int b_nrow = ((lane >> 4) << 3) + (lane & 7);     // B rows
    const int b_kb   = ((lane >> 3) & 1) << 4;
    const u32 xl     = (u32)((lane & 7) << 4);
    const u32 xk     = (u32)((a_krow & 7) << 4);

    const u32 bufs[2] = {sb + SM_B0, sb + SM_B1};

    // One tile (128 or 64 rows). mgroups = 4 (full) or 2 (half; warps 8..15 barrier-only).
    auto do_tile = [&](int pair, int eb, int mgroups) {
        const int s = pair >> 5, t = pair & 31;
        const bool act = (mgrp < mgroups);

        // ---- build h1 [128k][rows m] hi/lo ----
        if (mgroups == 4) {
            #pragma unroll
            for (int j = 0; j < 8; j++) {
                int k = wid + j * 16;
                float base = g_aT[s * H1 + k] + g_bT[t * H1 + k];
                u32 swz = (u32)((k & 7) << 4);
                int m = lane * 4;
                float4 c4 = *(const float4*)&g_cT[k * M_EDGES + eb + m];
                float v0 = fmaxf(base + c4.x, 0.f);
                float v1 = fmaxf(base + c4.y, 0.f);
                float v2 = fmaxf(base + c4.z, 0.f);
                float v3 = fmaxf(base + c4.w, 0.f);
                __nv_bfloat162 lp0, hp0 = split_hi(v0, v1, lp0);
                __nv_bfloat162 lp1, hp1 = split_hi(v2, v3, lp1);
                u32 off = ((u32)(k * 256 + m * 2)) ^ swz;
                *(__nv_bfloat162*)(smp + SM_A1H + off)     = hp0;
                *(__nv_bfloat162*)(smp + SM_A1H + off + 4) = hp1;
                *(__nv_bfloat162*)(smp + SM_A1L + off)     = lp0;
                *(__nv_bfloat162*)(smp + SM_A1L + off + 4) = lp1;
            }
        } else {
            // 64 rows: k = wid + 16*(lane>>4) + 32j, m = (lane&15)*4
            #pragma unroll
            for (int j = 0; j < 4; j++) {
                int k = wid + ((lane >> 4) << 4) + j * 32;
                float base = g_aT[s * H1 + k] + g_bT[t * H1 + k];
                u32 swz = (u32)((k & 7) << 4);
                int m = (lane & 15) * 4;
                float4 c4 = *(const float4*)&g_cT[k * M_EDGES + eb + m];
                float v0 = fmaxf(base + c4.x, 0.f);
                float v1 = fmaxf(base + c4.y, 0.f);
                float v2 = fmaxf(base + c4.z, 0.f);
                float v3 = fmaxf(base + c4.w, 0.f);
                __nv_bfloat162 lp0, hp0 = split_hi(v0, v1, lp0);
                __nv_bfloat162 lp1, hp1 = split_hi(v2, v3, lp1);
                u32 off = ((u32)(k * 256 + m * 2)) ^ swz;
                *(__nv_bfloat162*)(smp + SM_A1H + off)     = hp0;
                *(__nv_bfloat162*)(smp + SM_A1H + off + 4) = hp1;
                *(__nv_bfloat162*)(smp + SM_A1L + off)     = lp0;
                *(__nv_bfloat162*)(smp + SM_A1L + off + 4) = lp1;
            }
        }
        cp_wait0();
        __syncthreads();            // A1 ready + prefetched B2 piece 0 visible
                                    // (also guards A2 reuse vs prev tile's last L3)

        float acc3[2][4][4];
        #pragma unroll
        for (int mt = 0; mt < 2; mt++)
            #pragma unroll
            for (int nt = 0; nt < 4; nt++)
                #pragma unroll
                for (int i = 0; i < 4; i++) acc3[mt][nt][i] = 0.f;

        #pragma unroll 1
        for (int c = 0; c < 4; c++) {
            const u32 bb2 = bufs[0];       // even pieces -> buf0
            const u32 bb3 = bufs[1];       // odd pieces -> buf1

            // prefetch B3 sub c
            issue_piece(bb3, 2 * c + 1, tid);

            if (act) {
                // ---- L2 sub-MMA: acc2 = h1 x B2[:, c*64 .. c*64+64) ----
                float acc2[2][2][4];
                #pragma unroll
                for (int mt = 0; mt < 2; mt++)
                    #pragma unroll
                    for (int nt = 0; nt < 2; nt++)
                        #pragma unroll
                        for (int i = 0; i < 4; i++) acc2[mt][nt][i] = 0.f;

                #pragma unroll
                for (int ks = 0; ks < 8; ks++) {
                    u32 ah[2][4], al[2][4];
                    #pragma unroll
                    for (int mt = 0; mt < 2; mt++) {
                        u32 off = ((u32)((ks * 16 + a_krow) * 256 + (m0_2 + mt * 16) * 2 + a_cb)) ^ xk;
                        ldm_x4_t(ah[mt], sb + SM_A1H + off);
                        ldm_x4_t(al[mt], sb + SM_A1L + off);
                    }
                    u32 bh[4], bl[4];
                    {
                        u32 off = ((u32)((n0_2 + b_nrow) * 256 + ks * 32 + b_kb)) ^ xl;
                        ldm_x4(bh, bb2 + off);
                        ldm_x4(bl, bb2 + 16384 + off);
                    }
                    #pragma unroll
                    for (int mt = 0; mt < 2; mt++)
                        #pragma unroll
                        for (int nt = 0; nt < 2; nt++) {
                            const u32* Bh = &bh[nt * 2];
                            const u32* Bl = &bl[nt * 2];
                            mma16816(acc2[mt][nt], ah[mt], Bh);
                            mma16816(acc2[mt][nt], ah[mt], Bl);
                            mma16816(acc2[mt][nt], al[mt], Bh);
                        }
                }

                // ---- h2 epilogue -> A2 [rows m][64k] ----
                #pragma unroll
                for (int nt = 0; nt < 2; nt++) {
                    int nl = n0_2 + nt * 8 + (lane & 3) * 2;
                    int gc = c * 64 + nl;
                    float bx = __ldg(&b2[gc]), by = __ldg(&b2[gc + 1]);
                    #pragma unroll
                    for (int mt = 0; mt < 2; mt++) {
                        #pragma unroll
                        for (int h = 0; h < 2; h++) {
                            int row = m0_2 + mt * 16 + (lane >> 2) + h * 8;
                            float v0 = fmaxf(acc2[mt][nt][h * 2 + 0] + bx, 0.f);
                            float v1 = fmaxf(acc2[mt][nt][h * 2 + 1] + by, 0.f);
                            __nv_bfloat162 lp, hp = split_hi(v0, v1, lp);
                            u32 off = ((u32)(row * 128 + nl * 2)) ^ (u32)((row & 7) << 4);
                            *(__nv_bfloat162*)(smp + SM_A2H + off) = hp;
                            *(__nv_bfloat162*)(smp + SM_A2L + off) = lp;
                        }
                    }
                }
            }
            cp_wait0();
            __syncthreads();        // A2 visible + B3 piece ready

            // prefetch next even piece (wraps to 0 for next tile)
            issue_piece(bb2, (2 * c + 2) & 7, tid);

            if (act) {
                // ---- L3 sub-MMA: acc3 += h2c x B3[c*64.., :] ----
                #pragma unroll
                for (int ks = 0; ks < 4; ks++) {
                    u32 ah[2][4], al[2][4];
                    #pragma unroll
                    for (int mt = 0; mt < 2; mt++) {
                        u32 off = ((u32)((m0_3 + mt * 16 + a_row) * 128 + ks * 32 + a_kb3)) ^ xl;
                        ldm_x4(ah[mt], sb + SM_A2H + off);
                        ldm_x4(al[mt], sb + SM_A2L + off);
                    }
                    u32 bh[2][4], bl[2][4];
                    #pragma unroll
                    for (int np = 0; np < 2; np++) {
                        u32 off = ((u32)((n0_3 + np * 16 + b_nrow) * 128 + ks * 32 + b_kb)) ^ xl;
                        ldm_x4(bh[np], bb3 + off);
                        ldm_x4(bl[np], bb3 + 16384 + off);
                    }
                    #pragma unroll
                    for (int mt = 0; mt < 2; mt++)
                        #pragma unroll
                        for (int nt = 0; nt < 4; nt++) {
                            const u32* Bh = &bh[nt >> 1][(nt & 1) * 2];
                            const u32* Bl = &bl[nt >> 1][(nt & 1) * 2];
                            mma16816(acc3[mt][nt], ah[mt], Bh);
                            mma16816(acc3[mt][nt], ah[mt], Bl);
                            mma16816(acc3[mt][nt], al[mt], Bh);
                        }
                }
            }
            if (c < 3) {            // last chunk: covered by next tile's post-h1 barrier
                cp_wait0();
                __syncthreads();    // A2 free for next epilogue + next B2 ready
            }
        }

        // ---- layer 4: partial pred per warp-column -> g_preds4 (no barriers) ----
        if (act) {
            #pragma unroll
            for (int mt = 0; mt < 2; mt++) {
                #pragma unroll
                for (int h = 0; h < 2; h++) {
                    float part = 0.f;
                    #pragma unroll
                    for (int nt = 0; nt < 4; nt++) {
                        int cc = n0_3 + nt * 8 + (lane & 3) * 2;
                        float h0 = fmaxf(acc3[mt][nt][h * 2 + 0] + __ldg(&b3[cc]), 0.f);
                        float h1 = fmaxf(acc3[mt][nt][h * 2 + 1] + __ldg(&b3[cc + 1]), 0.f);
                        part = fmaf(h0, __ldg(&W4[cc]), part);
                        part = fmaf(h1, __ldg(&W4[cc + 1]), part);
                    }
                    part += __shfl_xor_sync(0xffffffffu, part, 1);
                    part += __shfl_xor_sync(0xffffffffu, part, 2);
                    if ((lane & 3) == 0) {
                        int row = m0_3 + mt * 16 + (lane >> 2) + h * 8;
                        g_preds4[wn3][pair * M_EDGES + eb + row] = part;
                    }
                }
            }
        }
    };

    // prefetch piece 0 into buf 0
    issue_piece(bufs[0], 0, tid);

    // ---- 13 uniform full tiles per CTA ----
    int tile = bid;
    #pragma unroll 1
    for (int i = 0; i < FULL_ROUNDS; i++, tile += GRID_MLP)
        do_tile(tile >> 1, (tile & 1) * 128, 4);

    // ---- remainder: 144 half-tiles (tiles 1976..2047 split in two) ----
    if (bid < NHALF) {
        int t2 = GRID_MLP * FULL_ROUNDS + (bid >> 1);
        do_tile(t2 >> 1, (t2 & 1) * 128 + (bid & 1) * 64, 2);
    }
    cp_wait0();
}

// ---------------- kernel 3: fused partial-sum + scatter + power iteration + final reduce ----------------
// grid 128 x 256: one warp per (s,t) pair; last CTA to finish also does the global reduction.
__global__ void power_kernel(const int* __restrict__ edges, const float* __restrict__ b4,
                             float* __restrict__ out)
{
    __shared__ float As[8][1024];
    __shared__ float red2[8][33];
    __shared__ int   isLast;
    const int wid  = threadIdx.x >> 5;
    const int lane = threadIdx.x & 31;
    const int p    = blockIdx.x * 8 + wid;
    float* A = As[wid];
    const float b4v = __ldg(&b4[0]);

    #pragma unroll
    for (int i = lane; i < 1024; i += 32) A[i] = 0.f;
    __syncwarp();

    #pragma unroll
    for (int j = 0; j < 8; j++) {
        int e = j * 32 + lane;
        int base = p * M_EDGES + e;
        float pred = ((g_preds4[0][base] + g_preds4[1][base])
                    + (g_preds4[2][base] + g_preds4[3][base])) + b4v;
        int u = edges[2 * e], v = edges[2 * e + 1];
        atomicAdd(&A[u * 32 + v], pred);
    }
    __syncwarp();

    const int s = p >> 5, t = p & 31;
    if (lane == 0) A[s * 32 + s] += 1.f;
    __syncwarp();

    float col[32];                       // A[:, lane]
    #pragma unroll
    for (int u = 0; u < 32; u++) col[u] = A[u * 32 + lane];

    // Power iteration with sparse normalization (direction-preserving scalar).
    float x = 1.0f / 32.0f;
    #pragma unroll 1
    for (int it = 0; it < 50; it++) {
        float a0 = 0.f, a1 = 0.f, a2 = 0.f, a3 = 0.f;
        #pragma unroll
        for (int u = 0; u < 32; u += 4) {
            a0 = fmaf(__shfl_sync(0xffffffffu, x, u),     col[u],     a0);
            a1 = fmaf(__shfl_sync(0xffffffffu, x, u + 1), col[u + 1], a1);
            a2 = fmaf(__shfl_sync(0xffffffffu, x, u + 2), col[u + 2], a2);
            a3 = fmaf(__shfl_sync(0xffffffffu, x, u + 3), col[u + 3], a3);
        }
        float acc = (a0 + a1) + (a2 + a3);
        if (((it & 3) == 3) || it == 49) {
            float ss = acc * acc;
            #pragma unroll
            for (int o = 16; o > 0; o >>= 1)
                ss += __shfl_xor_sync(0xffffffffu, ss, o);
            x = acc / (sqrtf(ss) + EPSF);
        } else {
            x = acc;
        }
    }
    float xs = __shfl_sync(0xffffffffu, x, s);
    float d = (s != t) ? x / (xs + EPSF) : 0.f;
    g_delta[p * 32 + lane] = d;

    // ---- last-block-done global reduction (deterministic order) ----
    __syncthreads();
    if (threadIdx.x == 0) {
        __threadfence();
        int done = atomicAdd(&g_ctr, 1);
        isLast = (done == gridDim.x - 1) ? 1 : 0;
    }
    __syncthreads();
    if (isLast) {
        __threadfence();
        int v = threadIdx.x & 31, g = threadIdx.x >> 5;   // 8 groups x 32
        float acc = 0.f;
        #pragma unroll 8
        for (int pp = g; pp < NPAIR; pp += 8)
            acc += g_delta[pp * 32 + v];
        red2[g][v] = acc;
        __syncthreads();
        if (g == 0) {
            float r = ((red2[0][v] + red2[1][v]) + (red2[2][v] + red2[3][v]))
                    + ((red2[4][v] + red2[5][v]) + (red2[6][v] + red2[7][v]));
            float tot = r;
            #pragma unroll
            for (int o = 16; o > 0; o >>= 1)
                tot += __shfl_xor_sync(0xffffffffu, tot, o);
            out[v] = r / tot;
        }
    }
}

// ---------------- launch ----------------
extern "C" void kernel_launch(void* const* d_in, const int* in_sizes, int n_in,
                              void* d_out, int out_size)
{
    (void)in_sizes; (void)n_in; (void)out_size;
    const float* emb   = (const float*)d_in[1];
    const int*   edges = (const int*)  d_in[2];
    const float* W1 = (const float*)d_in[3];
    const float* b1 = (const float*)d_in[4];
    const float* W2 = (const float*)d_in[5];
    const float* b2 = (const float*)d_in[6];
    const float* W3 = (const float*)d_in[7];
    const float* b3 = (const float*)d_in[8];
    const float* W4 = (const float*)d_in[9];
    const float* b4 = (const float*)d_in[10];
    float* out = (float*)d_out;

    static int attr_set = 0;
    if (!attr_set) {
        cudaFuncSetAttribute(mlp_fused_kernel, cudaFuncAttributeMaxDynamicSharedMemorySize, SM_TOTAL);
        attr_set = 1;
    }

    prep_all_kernel <<<416, 256>>>(emb, edges, W1, b1, W2, W3);
    mlp_fused_kernel<<<GRID_MLP, NTHREADS, SM_TOTAL>>>(b2, b3, W4);
    power_kernel    <<<128, 256>>>(edges, b4, out);
}